// round 7
// baseline (speedup 1.0000x reference)
#include <cuda_runtime.h>
#include <cuda_bf16.h>
#include <cstdint>

// Problem constants: B=64, T=512, I=256, H=512, L=3, C=1000
#define HID   512
#define GDIM  2048
#define MROWS 32768           // B*T
#define NCLS  1000

// ----------------- static device scratch (no allocations allowed) -----------------
__device__ float g_xg[(size_t)MROWS * GDIM];    // 256 MB: per-layer input projections
__device__ float g_hout[(size_t)MROWS * HID];   // 64 MB: layer output (next layer's input)
__device__ float g_hcur[2 * 64 * HID];          // ping-pong h_t (compact)
__device__ int   g_flags[3 * 512];              // per-layer per-step barrier counters

// ----------------- helpers -----------------
__device__ __forceinline__ uint32_t f2tf(float x) {
    uint32_t u; asm("cvt.rna.tf32.f32 %0, %1;" : "=r"(u) : "f"(x)); return u;
}
__device__ __forceinline__ void mma_tf32(float* d, const uint32_t* a, const uint32_t* b) {
    asm volatile("mma.sync.aligned.m16n8k8.row.col.f32.tf32.tf32.f32 "
        "{%0,%1,%2,%3}, {%4,%5,%6,%7}, {%8,%9}, {%0,%1,%2,%3};"
        : "+f"(d[0]), "+f"(d[1]), "+f"(d[2]), "+f"(d[3])
        : "r"(a[0]), "r"(a[1]), "r"(a[2]), "r"(a[3]), "r"(b[0]), "r"(b[1]));
}
__device__ __forceinline__ float sigmoid_f(float x) {
    return 1.0f / (1.0f + __expf(-x));
}
__device__ __forceinline__ float tanh_f(float x) {
    float e = __expf(-2.0f * fabsf(x));
    float r = (1.0f - e) / (1.0f + e);
    return copysignf(r, x);
}

// ----------------- flag reset -----------------
__global__ void zero_flags_kernel() {
    int i = blockIdx.x * blockDim.x + threadIdx.x;
    if (i < 3 * 512) g_flags[i] = 0;
}

// ----------------- input-projection GEMM -----------------
// g_xg[m, n] = sum_k A[m,k] * W[n,k] + bih[n] + bhh[n];  M=32768, N=2048, K in {256,512}
// CTA tile 128x64, 8 warps (4x2), warp tile 32x32, BK=32, tf32 mma m16n8k8.
__global__ __launch_bounds__(256) void gemm_xg_kernel(
    const float* __restrict__ Aext, const float* __restrict__ W,
    const float* __restrict__ bih, const float* __restrict__ bhh,
    int K, int a_sel)
{
    const float* __restrict__ A = a_sel ? (const float*)g_hout : Aext;

    __shared__ uint32_t a_s[128 * 36];
    __shared__ uint32_t b_s[64 * 36];
    __shared__ float bias_s[64];

    const int tid  = threadIdx.x;
    const int warp = tid >> 5, lane = tid & 31;
    const int grp  = lane >> 2, tig = lane & 3;
    const int m0 = blockIdx.y * 128, n0 = blockIdx.x * 64;
    const int wm = (warp >> 1) * 32, wn = (warp & 1) * 32;

    if (tid < 64) bias_s[tid] = bih[n0 + tid] + bhh[n0 + tid];

    float acc[2][4][4];
    #pragma unroll
    for (int mf = 0; mf < 2; ++mf)
        #pragma unroll
        for (int nf = 0; nf < 4; ++nf)
            #pragma unroll
            for (int r = 0; r < 4; ++r) acc[mf][nf][r] = 0.f;

    for (int kb = 0; kb < K; kb += 32) {
        float4 av[4], bv[2];
        #pragma unroll
        for (int i = 0; i < 4; ++i) {
            int idx = i * 256 + tid; int r = idx >> 3, kq = idx & 7;
            av[i] = *(const float4*)(A + (size_t)(m0 + r) * K + kb + kq * 4);
        }
        #pragma unroll
        for (int i = 0; i < 2; ++i) {
            int idx = i * 256 + tid; int r = idx >> 3, kq = idx & 7;
            bv[i] = *(const float4*)(W + (size_t)(n0 + r) * K + kb + kq * 4);
        }
        __syncthreads();   // previous iteration's smem reads complete
        #pragma unroll
        for (int i = 0; i < 4; ++i) {
            int idx = i * 256 + tid; int r = idx >> 3, kq = idx & 7;
            *(uint4*)&a_s[r * 36 + kq * 4] =
                make_uint4(f2tf(av[i].x), f2tf(av[i].y), f2tf(av[i].z), f2tf(av[i].w));
        }
        #pragma unroll
        for (int i = 0; i < 2; ++i) {
            int idx = i * 256 + tid; int r = idx >> 3, kq = idx & 7;
            *(uint4*)&b_s[r * 36 + kq * 4] =
                make_uint4(f2tf(bv[i].x), f2tf(bv[i].y), f2tf(bv[i].z), f2tf(bv[i].w));
        }
        __syncthreads();
        #pragma unroll
        for (int kt = 0; kt < 4; ++kt) {
            const int k0 = kt * 8;
            uint32_t af[2][4], bf[4][2];
            #pragma unroll
            for (int mf = 0; mf < 2; ++mf) {
                int rb = wm + mf * 16;
                af[mf][0] = a_s[(rb + grp) * 36 + k0 + tig];
                af[mf][1] = a_s[(rb + grp + 8) * 36 + k0 + tig];
                af[mf][2] = a_s[(rb + grp) * 36 + k0 + tig + 4];
                af[mf][3] = a_s[(rb + grp + 8) * 36 + k0 + tig + 4];
            }
            #pragma unroll
            for (int nf = 0; nf < 4; ++nf) {
                bf[nf][0] = b_s[(wn + nf * 8 + grp) * 36 + k0 + tig];
                bf[nf][1] = b_s[(wn + nf * 8 + grp) * 36 + k0 + tig + 4];
            }
            #pragma unroll
            for (int mf = 0; mf < 2; ++mf)
                #pragma unroll
                for (int nf = 0; nf < 4; ++nf)
                    mma_tf32(acc[mf][nf], af[mf], bf[nf]);
        }
    }

    #pragma unroll
    for (int mf = 0; mf < 2; ++mf) {
        #pragma unroll
        for (int nf = 0; nf < 4; ++nf) {
            int r0 = m0 + wm + mf * 16 + grp;
            int cl = wn + nf * 8 + 2 * tig;
            float2 v0 = make_float2(acc[mf][nf][0] + bias_s[cl], acc[mf][nf][1] + bias_s[cl + 1]);
            float2 v1 = make_float2(acc[mf][nf][2] + bias_s[cl], acc[mf][nf][3] + bias_s[cl + 1]);
            *(float2*)(g_xg + (size_t)r0 * GDIM + n0 + cl) = v0;
            *(float2*)(g_xg + (size_t)(r0 + 8) * GDIM + n0 + cl) = v1;
        }
    }
}

// ----------------- persistent recurrent kernel (one launch per layer) -----------------
// 64 CTAs (all co-resident: 1/SM, 64 <= 148 SMs), 256 threads. CTA c owns hidden
// units [c*8, c*8+8) = gate rows {q*512 + c*8 + j}. W_hh slice resident in SMEM
// (tf32) for all 512 steps; cell state in registers; per-step grid barrier via
// g_flags counters.
//
// Warp layout: 8 warps = 2 m-positions (32 batches each) x 4 k-slices (128 k each).
// Warp tile m32 x n32 x k128 -> SMEM operand traffic 256 KB/CTA/step (half of the
// m16n16 variant). k-split partials combined via two SMEM buffers + one RMW phase.
//
// Cross-CTA h traffic uses __ldcg/__stcg: within a persistent kernel L1 is NOT
// flushed, and plain loads can serve stale data cached two steps earlier.
#define RW_S 516                               // W_s/h_s row stride (words), conflict-free
#define RG_S 34                                // gate buffer row stride (words, even for float2)
#define REC_SMEM ((32*RW_S + 64*RW_S + 2*64*RG_S) * 4)   // 215552 B

__global__ __launch_bounds__(256, 1) void lstm_rec_kernel(
    const float* __restrict__ Whh, int layer, int whout)
{
    extern __shared__ uint32_t smem[];
    uint32_t* W_s = smem;                         // 32 x RW_S (tf32 bits)
    uint32_t* h_s = smem + 32 * RW_S;             // 64 x RW_S (tf32 bits)
    float*    g0  = (float*)(smem + 96 * RW_S);            // 64 x RG_S
    float*    g1  = (float*)(smem + 96 * RW_S + 64 * RG_S);

    const int tid = threadIdx.x;
    const int cta = blockIdx.x;
    const int u0  = cta * 8;
    const int warp = tid >> 5, lane = tid & 31;
    const int grp = lane >> 2, tig = lane & 3;
    const int wm = (warp >> 2) * 32;              // m position: batches [wm, wm+32)
    const int ks = warp & 3;                      // k slice: [ks*128, ks*128+128)
    const int kbase = ks * 128;
    float* gbuf = (ks < 2) ? g0 : g1;
    const bool writer = (ks == 0) || (ks == 2);
    const int b  = tid & 63, jp = tid >> 6;       // elementwise mapping

    // Load W_hh slice: local row n = q*8 + j  <->  global gate row q*512 + u0 + j
    for (int i = tid; i < 32 * 512; i += 256) {
        int n = i >> 9, k = i & 511;
        int gr = (n >> 3) * 512 + u0 + (n & 7);
        W_s[n * RW_S + k] = f2tf(Whh[(size_t)gr * 512 + k]);
    }
    __syncthreads();

    int* flags = g_flags + layer * 512;
    volatile int* vflags = flags;

    float c0 = 0.f, c1 = 0.f;

    for (int t = 0; t < 512; ++t) {
        // prefetch this thread's 8 xg values (independent of the barrier; DRAM
        // latency hides under spin + staging + MMA). Safe vs L1: each xg address
        // is read exactly once in this kernel, and the writer was a prior launch.
        float xv[8];
        const float* xrow = g_xg + (size_t)(b * 512 + t) * GDIM + u0 + jp * 2;
        #pragma unroll
        for (int q = 0; q < 4; ++q) {
            xv[q * 2 + 0] = xrow[q * 512 + 0];
            xv[q * 2 + 1] = xrow[q * 512 + 1];
        }

        if (t > 0) {
            if (tid == 0) {
                while (vflags[t - 1] != 64) { __nanosleep(64); }
            }
            __syncthreads();
            __threadfence();

            // stage h_{t-1}: 64x512 fp32 -> tf32 bits in SMEM (L2 reads: __ldcg)
            const float4* src = (const float4*)(g_hcur + ((t - 1) & 1) * (64 * HID));
            #pragma unroll 4
            for (int i = tid; i < 8192; i += 256) {
                int row = i >> 7, c4 = (i & 127) * 4;
                float4 v = __ldcg(src + i);
                *(uint4*)(h_s + row * RW_S + c4) =
                    make_uint4(f2tf(v.x), f2tf(v.y), f2tf(v.z), f2tf(v.w));
            }
            __syncthreads();

            // MMA: g[64 batch x 32 gate rows] += h_{t-1} @ Whh_slice^T (k-sliced)
            float acc[2][4][4];
            #pragma unroll
            for (int mf = 0; mf < 2; ++mf)
                #pragma unroll
                for (int nf = 0; nf < 4; ++nf)
                    #pragma unroll
                    for (int r = 0; r < 4; ++r) acc[mf][nf][r] = 0.f;

            #pragma unroll 2
            for (int ki = 0; ki < 16; ++ki) {
                const int kk = kbase + ki * 8;
                uint32_t a[2][4], bfr[4][2];
                #pragma unroll
                for (int mf = 0; mf < 2; ++mf) {
                    const uint32_t* ha = h_s + (wm + mf * 16 + grp) * RW_S + kk + tig;
                    a[mf][0] = ha[0];
                    a[mf][1] = ha[8 * RW_S];
                    a[mf][2] = ha[4];
                    a[mf][3] = ha[8 * RW_S + 4];
                }
                #pragma unroll
                for (int nf = 0; nf < 4; ++nf) {
                    const uint32_t* wb = W_s + (nf * 8 + grp) * RW_S + kk + tig;
                    bfr[nf][0] = wb[0];
                    bfr[nf][1] = wb[4];
                }
                #pragma unroll
                for (int mf = 0; mf < 2; ++mf)
                    #pragma unroll
                    for (int nf = 0; nf < 4; ++nf)
                        mma_tf32(acc[mf][nf], a[mf], bfr[nf]);
            }

            // combine k-slice partials: ks0->g0, ks2->g1; then ks1 += g0, ks3 += g1
            if (writer) {
                #pragma unroll
                for (int mf = 0; mf < 2; ++mf)
                    #pragma unroll
                    for (int nf = 0; nf < 4; ++nf) {
                        int r = (wm + mf * 16 + grp) * RG_S + nf * 8 + 2 * tig;
                        *(float2*)(gbuf + r) = make_float2(acc[mf][nf][0], acc[mf][nf][1]);
                        *(float2*)(gbuf + r + 8 * RG_S) = make_float2(acc[mf][nf][2], acc[mf][nf][3]);
                    }
            }
            __syncthreads();
            if (!writer) {
                #pragma unroll
                for (int mf = 0; mf < 2; ++mf)
                    #pragma unroll
                    for (int nf = 0; nf < 4; ++nf) {
                        int r = (wm + mf * 16 + grp) * RG_S + nf * 8 + 2 * tig;
                        float2 p0 = *(float2*)(gbuf + r);
                        float2 p1 = *(float2*)(gbuf + r + 8 * RG_S);
                        p0.x += acc[mf][nf][0]; p0.y += acc[mf][nf][1];
                        p1.x += acc[mf][nf][2]; p1.y += acc[mf][nf][3];
                        *(float2*)(gbuf + r) = p0;
                        *(float2*)(gbuf + r + 8 * RG_S) = p1;
                    }
            }
            __syncthreads();
        }

        // elementwise: thread handles (batch b, units j = 2jp, 2jp+1)
        float hv[2];
        #pragma unroll
        for (int jj = 0; jj < 2; ++jj) {
            int j = jp * 2 + jj;
            float gi = xv[0 + jj], gf = xv[2 + jj], gg = xv[4 + jj], go = xv[6 + jj];
            if (t > 0) {
                gi += g0[b * RG_S + 0 + j]  + g1[b * RG_S + 0 + j];
                gf += g0[b * RG_S + 8 + j]  + g1[b * RG_S + 8 + j];
                gg += g0[b * RG_S + 16 + j] + g1[b * RG_S + 16 + j];
                go += g0[b * RG_S + 24 + j] + g1[b * RG_S + 24 + j];
            }
            float iv = sigmoid_f(gi), fv = sigmoid_f(gf), ov = sigmoid_f(go);
            float gt = tanh_f(gg);
            float& cc = jj ? c1 : c0;
            cc = fv * cc + iv * gt;
            hv[jj] = ov * tanh_f(cc);
        }

        // publish h_t to L2 (__stcg: other SMs read it next step)
        __stcg((float2*)(g_hcur + (t & 1) * (64 * HID) + b * HID + u0 + jp * 2),
               make_float2(hv[0], hv[1]));
        if (whout) {
            float* ho = g_hout + (size_t)(b * 512 + t) * HID + u0 + jp * 2;
            ho[0] = hv[0]; ho[1] = hv[1];
        }

        __threadfence();
        __syncthreads();
        if (tid == 0) atomicAdd(&flags[t], 1);
    }
}

// ----------------- FC head: out[64,1000] = h_last @ W_fc^T + b_fc -----------------
__global__ __launch_bounds__(256) void fc_kernel(
    const float* __restrict__ Wfc, const float* __restrict__ bfc, float* __restrict__ out)
{
    __shared__ __align__(16) float Ws[4 * 512];
    const int tid = threadIdx.x;
    const int c0 = blockIdx.x * 4;

    for (int i = tid; i < 2048; i += 256) {
        int cc = i >> 9, k = i & 511;
        Ws[i] = (c0 + cc < NCLS) ? Wfc[(size_t)(c0 + cc) * 512 + k] : 0.f;
    }
    __syncthreads();

    int b = tid & 63, ci = tid >> 6;
    int c = c0 + ci;
    if (c < NCLS) {
        // h at t=511 lives in g_hcur parity 1 (511 & 1 == 1)
        const float4* hvp = (const float4*)(g_hcur + 64 * HID + b * HID);
        const float4* wvp = (const float4*)(Ws + ci * 512);
        float acc = 0.f;
        #pragma unroll 8
        for (int k = 0; k < 128; ++k) {
            float4 h4 = hvp[k], w4 = wvp[k];
            acc += h4.x * w4.x + h4.y * w4.y + h4.z * w4.z + h4.w * w4.w;
        }
        out[b * NCLS + c] = acc + bfc[c];
    }
}

// ----------------- launch -----------------
extern "C" void kernel_launch(void* const* d_in, const int* in_sizes, int n_in,
                              void* d_out, int out_size)
{
    const float* x     = (const float*)d_in[0];
    const float* Wih0  = (const float*)d_in[1];
    const float* Whh0  = (const float*)d_in[2];
    const float* bih0  = (const float*)d_in[3];
    const float* bhh0  = (const float*)d_in[4];
    const float* Wih1  = (const float*)d_in[5];
    const float* Whh1  = (const float*)d_in[6];
    const float* bih1  = (const float*)d_in[7];
    const float* bhh1  = (const float*)d_in[8];
    const float* Wih2  = (const float*)d_in[9];
    const float* Whh2  = (const float*)d_in[10];
    const float* bih2  = (const float*)d_in[11];
    const float* bhh2  = (const float*)d_in[12];
    const float* Wfc   = (const float*)d_in[13];
    const float* bfc   = (const float*)d_in[14];
    float* out = (float*)d_out;

    cudaFuncSetAttribute(lstm_rec_kernel,
                         cudaFuncAttributeMaxDynamicSharedMemorySize, REC_SMEM);

    dim3 ggrid(32, 256);

    zero_flags_kernel<<<3, 512>>>();

    // layer 0
    gemm_xg_kernel<<<ggrid, 256>>>(x, Wih0, bih0, bhh0, 256, 0);
    lstm_rec_kernel<<<64, 256, REC_SMEM>>>(Whh0, 0, 1);
    // layer 1
    gemm_xg_kernel<<<ggrid, 256>>>(nullptr, Wih1, bih1, bhh1, 512, 1);
    lstm_rec_kernel<<<64, 256, REC_SMEM>>>(Whh1, 1, 1);
    // layer 2 (no hout needed; only final-step h)
    gemm_xg_kernel<<<ggrid, 256>>>(nullptr, Wih2, bih2, bhh2, 512, 1);
    lstm_rec_kernel<<<64, 256, REC_SMEM>>>(Whh2, 2, 0);
    // FC head
    fc_kernel<<<250, 256>>>(Wfc, bfc, out);
}

// round 12
// speedup vs baseline: 1.1918x; 1.1918x over previous
#include <cuda_runtime.h>
#include <cuda_bf16.h>
#include <cstdint>

// Problem: B=64, T=512, I=256, H=512, L=3, C=1000
#define HID   512
#define GDIM  2048
#define MROWS 32768           // B*T
#define NCLS  1000

// xg layout: addr = t*131072 + g*2048 + b*32 + row, row = gate*8 + j, g = unit/8
// g_hcur layout: [parity][b][kperm(u)]  (k-pair-permuted for LDS.64 mma frags)

// ----------------- static device scratch -----------------
__device__ float g_xg[(size_t)MROWS * GDIM];    // 256 MB
__device__ float g_hout[(size_t)MROWS * HID];   // 64 MB (standard [b][t][u] layout)
__device__ float g_hcur[2 * 64 * HID];          // ping-pong h_t (permuted layout)
__device__ int   g_flags[3 * 512];              // per-layer per-step barrier counters

// ----------------- helpers -----------------
__device__ __forceinline__ uint32_t f2tf(float x) {
    uint32_t u; asm("cvt.rna.tf32.f32 %0, %1;" : "=r"(u) : "f"(x)); return u;
}
__device__ __host__ __forceinline__ int kperm(int k) {
    // within each 8-group, order [0,4,1,5,2,6,3,7] so (tig, tig+4) are adjacent
    return (k & ~7) | ((k & 3) << 1) | ((k >> 2) & 1);
}
__device__ __forceinline__ void mma_tf32(float* d, const uint32_t* a, const uint32_t* b) {
    asm volatile("mma.sync.aligned.m16n8k8.row.col.f32.tf32.tf32.f32 "
        "{%0,%1,%2,%3}, {%4,%5,%6,%7}, {%8,%9}, {%0,%1,%2,%3};"
        : "+f"(d[0]), "+f"(d[1]), "+f"(d[2]), "+f"(d[3])
        : "r"(a[0]), "r"(a[1]), "r"(a[2]), "r"(a[3]), "r"(b[0]), "r"(b[1]));
}
__device__ __forceinline__ float sigmoid_f(float x) {
    return 1.0f / (1.0f + __expf(-x));
}
__device__ __forceinline__ float tanh_f(float x) {
    float e = __expf(-2.0f * fabsf(x));
    float r = (1.0f - e) / (1.0f + e);
    return copysignf(r, x);
}

// ----------------- flag reset -----------------
__global__ void zero_flags_kernel() {
    int i = blockIdx.x * blockDim.x + threadIdx.x;
    if (i < 3 * 512) g_flags[i] = 0;
}

// ----------------- input-projection GEMM -----------------
// xg[t][g][b][row] = sum_k A[m,k]*W[n,k] + bih[n]+bhh[n];  m=b*512+t, n=q*512+u
// CTA tile 128x64, 8 warps (4x2), warp tile 32x32, BK=32, tf32 mma m16n8k8.
// Register-double-buffered global loads (next k-block issued before MMA).
__global__ __launch_bounds__(256) void gemm_xg_kernel(
    const float* __restrict__ Aext, const float* __restrict__ W,
    const float* __restrict__ bih, const float* __restrict__ bhh,
    int K, int a_sel)
{
    const float* __restrict__ A = a_sel ? (const float*)g_hout : Aext;

    __shared__ uint32_t a_s[128 * 36];
    __shared__ uint32_t b_s[64 * 36];
    __shared__ float bias_s[64];

    const int tid  = threadIdx.x;
    const int warp = tid >> 5, lane = tid & 31;
    const int grp  = lane >> 2, tig = lane & 3;
    const int m0 = blockIdx.y * 128, n0 = blockIdx.x * 64;
    const int wm = (warp >> 1) * 32, wn = (warp & 1) * 32;

    if (tid < 64) bias_s[tid] = bih[n0 + tid] + bhh[n0 + tid];

    float acc[2][4][4];
    #pragma unroll
    for (int mf = 0; mf < 2; ++mf)
        #pragma unroll
        for (int nf = 0; nf < 4; ++nf)
            #pragma unroll
            for (int r = 0; r < 4; ++r) acc[mf][nf][r] = 0.f;

    // preload kb=0
    float4 av[4], bv[2];
    #pragma unroll
    for (int i = 0; i < 4; ++i) {
        int idx = i * 256 + tid; int r = idx >> 3, kq = idx & 7;
        av[i] = *(const float4*)(A + (size_t)(m0 + r) * K + kq * 4);
    }
    #pragma unroll
    for (int i = 0; i < 2; ++i) {
        int idx = i * 256 + tid; int r = idx >> 3, kq = idx & 7;
        bv[i] = *(const float4*)(W + (size_t)(n0 + r) * K + kq * 4);
    }

    for (int kb = 0; kb < K; kb += 32) {
        __syncthreads();   // previous iteration's smem reads complete
        #pragma unroll
        for (int i = 0; i < 4; ++i) {
            int idx = i * 256 + tid; int r = idx >> 3, kq = idx & 7;
            *(uint4*)&a_s[r * 36 + kq * 4] =
                make_uint4(f2tf(av[i].x), f2tf(av[i].y), f2tf(av[i].z), f2tf(av[i].w));
        }
        #pragma unroll
        for (int i = 0; i < 2; ++i) {
            int idx = i * 256 + tid; int r = idx >> 3, kq = idx & 7;
            *(uint4*)&b_s[r * 36 + kq * 4] =
                make_uint4(f2tf(bv[i].x), f2tf(bv[i].y), f2tf(bv[i].z), f2tf(bv[i].w));
        }
        __syncthreads();

        // issue next block's loads before MMA (latency hides under tensor work)
        const bool more = (kb + 32) < K;
        float4 av2[4], bv2[2];
        if (more) {
            #pragma unroll
            for (int i = 0; i < 4; ++i) {
                int idx = i * 256 + tid; int r = idx >> 3, kq = idx & 7;
                av2[i] = *(const float4*)(A + (size_t)(m0 + r) * K + kb + 32 + kq * 4);
            }
            #pragma unroll
            for (int i = 0; i < 2; ++i) {
                int idx = i * 256 + tid; int r = idx >> 3, kq = idx & 7;
                bv2[i] = *(const float4*)(W + (size_t)(n0 + r) * K + kb + 32 + kq * 4);
            }
        }

        #pragma unroll
        for (int kt = 0; kt < 4; ++kt) {
            const int k0 = kt * 8;
            uint32_t af[2][4], bf[4][2];
            #pragma unroll
            for (int mf = 0; mf < 2; ++mf) {
                int rb = wm + mf * 16;
                af[mf][0] = a_s[(rb + grp) * 36 + k0 + tig];
                af[mf][1] = a_s[(rb + grp + 8) * 36 + k0 + tig];
                af[mf][2] = a_s[(rb + grp) * 36 + k0 + tig + 4];
                af[mf][3] = a_s[(rb + grp + 8) * 36 + k0 + tig + 4];
            }
            #pragma unroll
            for (int nf = 0; nf < 4; ++nf) {
                bf[nf][0] = b_s[(wn + nf * 8 + grp) * 36 + k0 + tig];
                bf[nf][1] = b_s[(wn + nf * 8 + grp) * 36 + k0 + tig + 4];
            }
            #pragma unroll
            for (int mf = 0; mf < 2; ++mf)
                #pragma unroll
                for (int nf = 0; nf < 4; ++nf)
                    mma_tf32(acc[mf][nf], af[mf], bf[nf]);
        }

        if (more) {
            #pragma unroll
            for (int i = 0; i < 4; ++i) av[i] = av2[i];
            #pragma unroll
            for (int i = 0; i < 2; ++i) bv[i] = bv2[i];
        }
    }

    // epilogue: write xg layout [t][g][b][row]; quads of tig-lanes are 32B-contiguous
    const int q  = n0 >> 9;            // gate (constant per CTA: n-tile never crosses 512)
    const int gb = (n0 & 511) >> 3;    // unit-group base
    #pragma unroll
    for (int mf = 0; mf < 2; ++mf) {
        int m1 = m0 + wm + mf * 16 + grp;
        int t1 = m1 & 511, b1 = m1 >> 9;     // b constant across m-tile (m0%512+127<512)
        size_t base1 = (size_t)t1 * 131072 + (size_t)b1 * 32;
        #pragma unroll
        for (int nf = 0; nf < 4; ++nf) {
            int cl = wn + nf * 8 + 2 * tig;
            int gg = gb + ((wn + nf * 8) >> 3);
            int row = q * 8 + 2 * tig;
            float bx = bias_s[cl], by = bias_s[cl + 1];
            size_t a1 = base1 + (size_t)gg * 2048 + row;
            *(float2*)(g_xg + a1) = make_float2(acc[mf][nf][0] + bx, acc[mf][nf][1] + by);
            *(float2*)(g_xg + a1 + (size_t)8 * 131072) =
                make_float2(acc[mf][nf][2] + bx, acc[mf][nf][3] + by);
        }
    }
}

// ----------------- persistent recurrent kernel (one launch per layer) -----------------
// 128 CTAs (co-resident: 1/SM, 128 <= 148). CTA (g = bid>>1, s = bid&1) owns units
// [g*8, g*8+8) for batches [s*32, s*32+32). W_hh slice (32 gate rows, k-permuted tf32)
// resident in SMEM; cell state in registers; per-step release/acquire flag barrier.
// 8 warps = 4 k-slices (k128) x 2 n-halves (n16); warp tile m32 x n16 x k128.
// Each warp stages its own 8KB h slice; named barrier per k-slice pair.
#define RW 516                                 // h_s/W_s row stride (words)
#define RB 34                                  // gate buffer row stride (words)
#define REC_SMEM ((32*RW*2 + 32*RB*2) * 4)     // 140800 B

__global__ __launch_bounds__(256, 1) void lstm_rec_kernel(
    const float* __restrict__ Whh, int layer, int whout)
{
    extern __shared__ uint32_t smem[];
    uint32_t* W_s  = smem;                       // 32 x RW
    uint32_t* h_s  = smem + 32 * RW;             // 32 x RW
    float*    buf0 = (float*)(smem + 64 * RW);   // 32 x RB
    float*    buf1 = buf0 + 32 * RB;             // 32 x RB

    const int tid  = threadIdx.x;
    const int g    = blockIdx.x >> 1, s = blockIdx.x & 1;
    const int u0   = g * 8;
    const int warp = tid >> 5, lane = tid & 31;
    const int grp  = lane >> 2, tig = lane & 3;
    const int ks   = warp & 3, nh = warp >> 2;
    const int b_   = tid & 31, j = tid >> 5;     // elementwise: (local batch, unit)
    const int bglob = s * 32 + b_;
    const int jperm = ((j & 3) << 1) | ((j >> 2) & 1);

    // W_hh slice: local row n = q*8 + jj <-> global gate row q*512 + u0 + jj; k permuted
    for (int i = tid; i < 32 * 512; i += 256) {
        int row = i >> 9, k = i & 511;
        int gr = (row >> 3) * 512 + u0 + (row & 7);
        W_s[row * RW + kperm(k)] = f2tf(Whh[(size_t)gr * 512 + k]);
    }
    __syncthreads();

    int* flags = g_flags + layer * 512;
    float cc = 0.f;
    const int kb = ks * 128 + nh * 64;           // this warp's staging k-range

    for (int t = 0; t < 512; ++t) {
        // xg prefetch (contiguous 4KB block per CTA; issued before the wait)
        float xv[4];
        {
            const float* xp = g_xg + (size_t)t * 131072 + (size_t)g * 2048 + bglob * 32 + j;
            #pragma unroll
            for (int qq = 0; qq < 4; ++qq) xv[qq] = xp[qq * 8];
        }

        if (t > 0) {
            if (tid == 0) {
                int v;
                do {
                    asm volatile("ld.acquire.gpu.global.s32 %0, [%1];"
                                 : "=r"(v) : "l"(flags + t - 1));
                } while (v < 128);
            }
            __syncthreads();

            // stage own 8KB slice: 32 rows x 64 k at offset kb (already k-permuted)
            const float* hsrc = g_hcur + ((t - 1) & 1) * (64 * HID) + (size_t)s * 32 * HID + kb;
            #pragma unroll
            for (int i = 0; i < 16; ++i) {
                int idx = i * 32 + lane;
                int row = idx >> 4, c4 = (idx & 15) * 4;
                float4 v = __ldcg((const float4*)(hsrc + row * HID + c4));
                *(uint4*)(h_s + row * RW + kb + c4) =
                    make_uint4(f2tf(v.x), f2tf(v.y), f2tf(v.z), f2tf(v.w));
            }
            asm volatile("bar.sync %0, 64;" :: "r"(1 + ks) : "memory");

            // MMA: m32 x n16(offset nh*16) x k128(offset ks*128)
            float acc[2][2][4];
            #pragma unroll
            for (int mf = 0; mf < 2; ++mf)
                #pragma unroll
                for (int nf = 0; nf < 2; ++nf)
                    #pragma unroll
                    for (int r = 0; r < 4; ++r) acc[mf][nf][r] = 0.f;

            const int k0 = ks * 128;
            #pragma unroll 4
            for (int ki = 0; ki < 16; ++ki) {
                const int kk = k0 + ki * 8 + 2 * tig;
                uint32_t Af[2][4], Bf[2][2];
                #pragma unroll
                for (int mf = 0; mf < 2; ++mf) {
                    uint2 lo = *(const uint2*)(h_s + (mf * 16 + grp) * RW + kk);
                    uint2 hi = *(const uint2*)(h_s + (mf * 16 + grp + 8) * RW + kk);
                    Af[mf][0] = lo.x; Af[mf][1] = hi.x; Af[mf][2] = lo.y; Af[mf][3] = hi.y;
                }
                #pragma unroll
                for (int nf = 0; nf < 2; ++nf) {
                    uint2 bb = *(const uint2*)(W_s + (nh * 16 + nf * 8 + grp) * RW + kk);
                    Bf[nf][0] = bb.x; Bf[nf][1] = bb.y;
                }
                #pragma unroll
                for (int mf = 0; mf < 2; ++mf)
                    #pragma unroll
                    for (int nf = 0; nf < 2; ++nf)
                        mma_tf32(acc[mf][nf], Af[mf], Bf[nf]);
            }

            // combine: ks0->buf0, ks2->buf1 (write); ks1->buf0, ks3->buf1 (RMW)
            float* mybuf = (ks & 2) ? buf1 : buf0;
            if (!(ks & 1)) {
                #pragma unroll
                for (int mf = 0; mf < 2; ++mf)
                    #pragma unroll
                    for (int nf = 0; nf < 2; ++nf) {
                        int m = mf * 16 + grp, n = nh * 16 + nf * 8 + 2 * tig;
                        *(float2*)(mybuf + m * RB + n) =
                            make_float2(acc[mf][nf][0], acc[mf][nf][1]);
                        *(float2*)(mybuf + (m + 8) * RB + n) =
                            make_float2(acc[mf][nf][2], acc[mf][nf][3]);
                    }
            }
            __syncthreads();
            if (ks & 1) {
                #pragma unroll
                for (int mf = 0; mf < 2; ++mf)
                    #pragma unroll
                    for (int nf = 0; nf < 2; ++nf) {
                        int m = mf * 16 + grp, n = nh * 16 + nf * 8 + 2 * tig;
                        float2 p0 = *(float2*)(mybuf + m * RB + n);
                        float2 p1 = *(float2*)(mybuf + (m + 8) * RB + n);
                        p0.x += acc[mf][nf][0]; p0.y += acc[mf][nf][1];
                        p1.x += acc[mf][nf][2]; p1.y += acc[mf][nf][3];
                        *(float2*)(mybuf + m * RB + n) = p0;
                        *(float2*)(mybuf + (m + 8) * RB + n) = p1;
                    }
            }
            __syncthreads();
        }

        // elementwise: thread (b_, j) — one hidden unit
        float gi = xv[0], gf = xv[1], gg = xv[2], go = xv[3];
        if (t > 0) {
            gi += buf0[b_ * RB + j]      + buf1[b_ * RB + j];
            gf += buf0[b_ * RB + 8 + j]  + buf1[b_ * RB + 8 + j];
            gg += buf0[b_ * RB + 16 + j] + buf1[b_ * RB + 16 + j];
            go += buf0[b_ * RB + 24 + j] + buf1[b_ * RB + 24 + j];
        }
        float iv = sigmoid_f(gi), fv = sigmoid_f(gf), ov = sigmoid_f(go);
        float gt = tanh_f(gg);
        cc = fv * cc + iv * gt;
        float hv = ov * tanh_f(cc);

        // publish h_t (k-pair-permuted layout) to L2
        __stcg(g_hcur + (t & 1) * (64 * HID) + bglob * HID + u0 + jperm, hv);
        if (whout)
            g_hout[((size_t)bglob * 512 + t) * HID + u0 + j] = hv;

        __syncthreads();
        if (tid == 0)
            asm volatile("red.release.gpu.global.add.s32 [%0], %1;"
                         :: "l"(flags + t), "r"(1) : "memory");
    }
}

// ----------------- FC head: out[64,1000] = h_last @ W_fc^T + b_fc -----------------
// h_last is in permuted layout -> load W_fc with the same k-permutation.
__global__ __launch_bounds__(256) void fc_kernel(
    const float* __restrict__ Wfc, const float* __restrict__ bfc, float* __restrict__ out)
{
    __shared__ __align__(16) float Ws[4 * 512];
    const int tid = threadIdx.x;
    const int c0 = blockIdx.x * 4;

    for (int i = tid; i < 2048; i += 256) {
        int cc = i >> 9, k = i & 511;
        Ws[cc * 512 + kperm(k)] = (c0 + cc < NCLS) ? Wfc[(size_t)(c0 + cc) * 512 + k] : 0.f;
    }
    __syncthreads();

    int b = tid & 63, ci = tid >> 6;
    int c = c0 + ci;
    if (c < NCLS) {
        // h at t=511 lives in parity 1
        const float4* hvp = (const float4*)(g_hcur + 64 * HID + b * HID);
        const float4* wvp = (const float4*)(Ws + ci * 512);
        float acc = 0.f;
        #pragma unroll 8
        for (int k = 0; k < 128; ++k) {
            float4 h4 = hvp[k], w4 = wvp[k];
            acc += h4.x * w4.x + h4.y * w4.y + h4.z * w4.z + h4.w * w4.w;
        }
        out[b * NCLS + c] = acc + bfc[c];
    }
}

// ----------------- launch -----------------
extern "C" void kernel_launch(void* const* d_in, const int* in_sizes, int n_in,
                              void* d_out, int out_size)
{
    const float* x     = (const float*)d_in[0];
    const float* Wih0  = (const float*)d_in[1];
    const float* Whh0  = (const float*)d_in[2];
    const float* bih0  = (const float*)d_in[3];
    const float* bhh0  = (const float*)d_in[4];
    const float* Wih1  = (const float*)d_in[5];
    const float* Whh1  = (const float*)d_in[6];
    const float* bih1  = (const float*)d_in[7];
    const float* bhh1  = (const float*)d_in[8];
    const float* Wih2  = (const float*)d_in[9];
    const float* Whh2  = (const float*)d_in[10];
    const float* bih2  = (const float*)d_in[11];
    const float* bhh2  = (const float*)d_in[12];
    const float* Wfc   = (const float*)d_in[13];
    const float* bfc   = (const float*)d_in[14];
    float* out = (float*)d_out;

    cudaFuncSetAttribute(lstm_rec_kernel,
                         cudaFuncAttributeMaxDynamicSharedMemorySize, REC_SMEM);

    dim3 ggrid(32, 256);

    zero_flags_kernel<<<3, 512>>>();

    // layer 0
    gemm_xg_kernel<<<ggrid, 256>>>(x, Wih0, bih0, bhh0, 256, 0);
    lstm_rec_kernel<<<128, 256, REC_SMEM>>>(Whh0, 0, 1);
    // layer 1
    gemm_xg_kernel<<<ggrid, 256>>>(nullptr, Wih1, bih1, bhh1, 512, 1);
    lstm_rec_kernel<<<128, 256, REC_SMEM>>>(Whh1, 1, 1);
    // layer 2 (only final-step h needed downstream)
    gemm_xg_kernel<<<ggrid, 256>>>(nullptr, Wih2, bih2, bhh2, 512, 1);
    lstm_rec_kernel<<<128, 256, REC_SMEM>>>(Whh2, 2, 0);
    // FC head
    fc_kernel<<<250, 256>>>(Wfc, bfc, out);
}

// round 13
// speedup vs baseline: 1.5183x; 1.2740x over previous
#include <cuda_runtime.h>
#include <cuda_bf16.h>
#include <cstdint>

// Problem: B=64, T=512, I=256, H=512, L=3, C=1000
#define HID   512
#define NCLS  1000

// ----------------- static device scratch -----------------
// h history: g_hh[layer][t][b][kperm(u)]  (k-pair-permuted unit index)
__device__ float g_hh[(size_t)3 * 512 * 64 * 512];   // 201 MB
__device__ int   g_flags[3 * 512];                   // per-layer per-step counters (43 arrivals)

// ----------------- helpers -----------------
__device__ __forceinline__ uint32_t f2tf(float x) {
    uint32_t u; asm("cvt.rna.tf32.f32 %0, %1;" : "=r"(u) : "f"(x)); return u;
}
// within each 8-block: [0,1,2,3,4,5,6,7] -> stored position [0,2,4,6,1,3,5,7]
// so stored pair (2p, 2p+1) = logical (p, p+4): uint2 loads feed mma k=tig, k=tig+4.
__device__ __forceinline__ int kperm(int k) {
    return (k & ~7) | ((k & 3) << 1) | ((k >> 2) & 1);
}
__device__ __forceinline__ void mma_tf32(float* d, const uint32_t* a, const uint32_t* b) {
    asm volatile("mma.sync.aligned.m16n8k8.row.col.f32.tf32.tf32.f32 "
        "{%0,%1,%2,%3}, {%4,%5,%6,%7}, {%8,%9}, {%0,%1,%2,%3};"
        : "+f"(d[0]), "+f"(d[1]), "+f"(d[2]), "+f"(d[3])
        : "r"(a[0]), "r"(a[1]), "r"(a[2]), "r"(a[3]), "r"(b[0]), "r"(b[1]));
}
__device__ __forceinline__ float sigmoid_f(float x) {
    return 1.0f / (1.0f + __expf(-x));
}
__device__ __forceinline__ float tanh_f(float x) {
    float e = __expf(-2.0f * fabsf(x));
    float r = (1.0f - e) / (1.0f + e);
    return copysignf(r, x);
}
__device__ __forceinline__ void pollflag(const int* p, int target) {
    int v;
    do {
        asm volatile("ld.acquire.gpu.global.s32 %0, [%1];" : "=r"(v) : "l"(p));
    } while (v < target);
}

// ----------------- flag reset -----------------
__global__ void zero_flags_kernel() {
    int i = blockIdx.x * blockDim.x + threadIdx.x;
    if (i < 3 * 512) g_flags[i] = 0;
}

// ----------------- fused 3-layer wavefront LSTM -----------------
// Grid = 129 CTAs (43 per layer), 256 threads, all co-resident (1 CTA/SM).
// CTA (layer, lc): owns units [lc*12, +12) (last CTA of each layer: 8 units).
// Gate preactivation  g = [cross | own] @ [W_ih | W_hh]^T + bias, where
//   cross = x_t (L0, K=256) or h_{l-1}[t] (L1/2, K=512); own = h_l[t-1] (K=512).
// W slice (nrows x K, tf32, k-permuted) resident in SMEM for all 512 steps.
// 8 warps: wm = w&3 (16-batch m-group), wn = w>>2 (n-half). wn==0 warp of each
// m-group stages that group's A rows in double-buffered 32-col chunks with
// 1-chunk register prefetch (LDG.cg -> STS next chunk during current mma).
// Flags: layer l step t waits flag[l-1][t] (if l>0) and flag[l][t-1] (if t>0);
// arrives on flag[l][t] via red.release.gpu after writing h to g_hh.
#define FUSED_SMEM 228800   // words: 48*1028 + 4*2*16*36 + 64*50 + 48 = 57200

__global__ __launch_bounds__(256, 1) void lstm_fused_kernel(
    const float* __restrict__ x,
    const float* __restrict__ Wih0, const float* __restrict__ Whh0,
    const float* __restrict__ bih0, const float* __restrict__ bhh0,
    const float* __restrict__ Wih1, const float* __restrict__ Whh1,
    const float* __restrict__ bih1, const float* __restrict__ bhh1,
    const float* __restrict__ Wih2, const float* __restrict__ Whh2,
    const float* __restrict__ bih2, const float* __restrict__ bhh2)
{
    extern __shared__ uint32_t sm[];

    const int tid   = threadIdx.x;
    const int bid   = blockIdx.x;
    const int layer = bid / 43, lc = bid % 43;
    const int nu    = (lc == 42) ? 8 : 12;
    const int u0    = lc * 12;
    const int nrows = 4 * nu;                 // 48 or 32
    const int ntl   = nu >> 2;                // n8-tiles per warp n-half: 3 or 2
    const int KX    = (layer == 0) ? 256 : 512;
    const int K     = KX + 512;               // 768 or 1024
    const int RWS   = K + 4;                  // W_s row stride (even)
    const int ckx   = KX >> 5, cktot = K >> 5;

    const float* Wcross = (layer == 0) ? Wih0 : ((layer == 1) ? Wih1 : Wih2);
    const float* Wown   = (layer == 0) ? Whh0 : ((layer == 1) ? Whh1 : Whh2);
    const float* bA     = (layer == 0) ? bih0 : ((layer == 1) ? bih1 : bih2);
    const float* bB     = (layer == 0) ? bhh0 : ((layer == 1) ? bhh1 : bhh2);

    uint32_t* W_s    = sm;                            // nrows x RWS (reserve 48 rows)
    uint32_t* st_s   = sm + 48 * RWS;                 // 4 mgroups x 2 bufs x 16 x 36
    float*    gbuf   = (float*)(sm + 48 * RWS + 4 * 2 * 16 * 36);  // 64 x 50
    float*    bias_s = gbuf + 64 * 50;                // 48

    const int w = tid >> 5, lane = tid & 31;
    const int grp = lane >> 2, tig = lane & 3;
    const int wm = w & 3;                    // m-group: batches [wm*16, +16)  (producers spread 1/SMSP)
    const int wn = w >> 2;                   // n-half
    const int bm0 = wm * 16;
    const bool producer = (wn == 0);

    // ---- init: W slice (k-permuted tf32) + bias ----
    for (int n = 0; n < nrows; ++n) {
        int gr = (n / nu) * 512 + u0 + (n % nu);     // global gate row
        for (int k = tid; k < K; k += 256) {
            float wv; int kk;
            if (k < KX) { wv = Wcross[(size_t)gr * KX + k];        kk = kperm(k); }
            else        { wv = Wown[(size_t)gr * 512 + (k - KX)];  kk = KX + kperm(k - KX); }
            W_s[n * RWS + kk] = f2tf(wv);
        }
    }
    if (tid < nrows) {
        int gr = (tid / nu) * 512 + u0 + (tid % nu);
        bias_s[tid] = bA[gr] + bB[gr];
    }
    __syncthreads();

    float cst[3] = {0.f, 0.f, 0.f};
    const int ne = (nu == 12) ? 3 : 2;

    for (int t = 0; t < 512; ++t) {
        // ---- dependency waits ----
        if (layer > 0 && tid == 0) pollflag(&g_flags[(layer - 1) * 512 + t], 43);
        if (t > 0 && tid == 32)    pollflag(&g_flags[layer * 512 + t - 1], 43);
        __syncthreads();

        const int nck = (t == 0) ? ckx : cktot;   // at t=0, own-h chunks are zero: skip

        // ---- chunk producer helpers (inlined via lambdas) ----
        float4 pf[4];
        auto ldg_chunk = [&](int ci) {
            #pragma unroll
            for (int it = 0; it < 4; ++it) {
                int linear = it * 32 + lane;
                int r = linear >> 3, colq = linear & 7;
                const float* sp;
                if (layer == 0 && ci < 8)
                    sp = x + ((size_t)(bm0 + r) * 512 + t) * 256 + ci * 32 + colq * 4;
                else if (ci < ckx)
                    sp = g_hh + (((size_t)(layer - 1) * 512 + t) * 64 + bm0 + r) * 512
                         + ci * 32 + colq * 4;
                else
                    sp = g_hh + (((size_t)layer * 512 + (t - 1)) * 64 + bm0 + r) * 512
                         + (ci - ckx) * 32 + colq * 4;
                pf[it] = __ldcg((const float4*)sp);
            }
        };
        auto sts_chunk = [&](int ci) {
            uint32_t* sb = st_s + (wm * 2 + (ci & 1)) * 576;
            #pragma unroll
            for (int it = 0; it < 4; ++it) {
                int linear = it * 32 + lane;
                int r = linear >> 3, colq = linear & 7;
                float4 v = pf[it];
                if (layer == 0 && ci < 8) {
                    // x is unpermuted in gmem: scatter with kperm
                    int base = r * 36 + ((colq >> 1) << 3) + (colq & 1);
                    sb[base + 0] = f2tf(v.x); sb[base + 2] = f2tf(v.y);
                    sb[base + 4] = f2tf(v.z); sb[base + 6] = f2tf(v.w);
                } else {
                    // h history already stored permuted
                    *(uint4*)(sb + r * 36 + colq * 4) =
                        make_uint4(f2tf(v.x), f2tf(v.y), f2tf(v.z), f2tf(v.w));
                }
            }
        };

        // ---- pipeline prologue ----
        if (producer) {
            ldg_chunk(0);
            sts_chunk(0);
            if (nck > 1) ldg_chunk(1);
        }
        __syncthreads();

        float acc[3][4];
        #pragma unroll
        for (int nf = 0; nf < 3; ++nf)
            #pragma unroll
            for (int r = 0; r < 4; ++r) acc[nf][r] = 0.f;

        // ---- chunk loop: stage p+1 / prefetch p+2 while mma p ----
        for (int p = 0; p < nck; ++p) {
            if (producer && p + 1 < nck) {
                sts_chunk(p + 1);
                if (p + 2 < nck) ldg_chunk(p + 2);
            }
            const uint32_t* ab = st_s + (wm * 2 + (p & 1)) * 576;
            const int wc = p * 32;
            #pragma unroll
            for (int k8 = 0; k8 < 4; ++k8) {
                const int kk = k8 * 8 + 2 * tig;
                uint2 lo = *(const uint2*)(ab + grp * 36 + kk);
                uint2 hi = *(const uint2*)(ab + (grp + 8) * 36 + kk);
                uint32_t Af[4] = {lo.x, hi.x, lo.y, hi.y};
                #pragma unroll
                for (int nf = 0; nf < 3; ++nf) {
                    if (nf < ntl) {
                        uint2 bb = *(const uint2*)(W_s + (wn * ntl * 8 + nf * 8 + grp) * RWS + wc + kk);
                        uint32_t Bf[2] = {bb.x, bb.y};
                        mma_tf32(acc[nf], Af, Bf);
                    }
                }
            }
            __syncthreads();
        }

        // ---- gate buffer ----
        #pragma unroll
        for (int nf = 0; nf < 3; ++nf) {
            if (nf < ntl) {
                int col = wn * ntl * 8 + nf * 8 + 2 * tig;
                *(float2*)&gbuf[(bm0 + grp) * 50 + col] =
                    make_float2(acc[nf][0], acc[nf][1]);
                *(float2*)&gbuf[(bm0 + grp + 8) * 50 + col] =
                    make_float2(acc[nf][2], acc[nf][3]);
            }
        }
        __syncthreads();

        // ---- elementwise gates + cell update + h store ----
        #pragma unroll
        for (int i = 0; i < 3; ++i) {
            if (i < ne) {
                int e = i * 256 + tid;
                int b = e & 63, j = e >> 6;
                float gi = gbuf[b * 50 + 0 * nu + j] + bias_s[0 * nu + j];
                float gf = gbuf[b * 50 + 1 * nu + j] + bias_s[1 * nu + j];
                float gg = gbuf[b * 50 + 2 * nu + j] + bias_s[2 * nu + j];
                float go = gbuf[b * 50 + 3 * nu + j] + bias_s[3 * nu + j];
                float iv = sigmoid_f(gi), fv = sigmoid_f(gf), ov = sigmoid_f(go);
                float gt = tanh_f(gg);
                cst[i] = fv * cst[i] + iv * gt;
                float hv = ov * tanh_f(cst[i]);
                int u = u0 + j;
                int pu = kperm(u);
                g_hh[(((size_t)layer * 512 + t) * 64 + b) * 512 + pu] = hv;
            }
        }

        __syncthreads();
        if (tid == 0)
            asm volatile("red.release.gpu.global.add.s32 [%0], %1;"
                         :: "l"(g_flags + layer * 512 + t), "r"(1) : "memory");
    }
}

// ----------------- FC head: out[64,1000] = h2[511] @ W_fc^T + b_fc -----------------
// h2 stored k-permuted -> load W_fc with the same permutation.
__global__ __launch_bounds__(256) void fc_kernel(
    const float* __restrict__ Wfc, const float* __restrict__ bfc, float* __restrict__ out)
{
    __shared__ __align__(16) float Ws[4 * 512];
    const int tid = threadIdx.x;
    const int c0 = blockIdx.x * 4;

    for (int i = tid; i < 2048; i += 256) {
        int cc = i >> 9, k = i & 511;
        Ws[cc * 512 + kperm(k)] = (c0 + cc < NCLS) ? Wfc[(size_t)(c0 + cc) * 512 + k] : 0.f;
    }
    __syncthreads();

    int b = tid & 63, ci = tid >> 6;
    int c = c0 + ci;
    if (c < NCLS) {
        const float4* hvp = (const float4*)(g_hh + (((size_t)2 * 512 + 511) * 64 + b) * 512);
        const float4* wvp = (const float4*)(Ws + ci * 512);
        float acc = 0.f;
        #pragma unroll 8
        for (int k = 0; k < 128; ++k) {
            float4 h4 = hvp[k], w4 = wvp[k];
            acc += h4.x * w4.x + h4.y * w4.y + h4.z * w4.z + h4.w * w4.w;
        }
        out[b * NCLS + c] = acc + bfc[c];
    }
}

// ----------------- launch -----------------
extern "C" void kernel_launch(void* const* d_in, const int* in_sizes, int n_in,
                              void* d_out, int out_size)
{
    const float* x     = (const float*)d_in[0];
    const float* Wih0  = (const float*)d_in[1];
    const float* Whh0  = (const float*)d_in[2];
    const float* bih0  = (const float*)d_in[3];
    const float* bhh0  = (const float*)d_in[4];
    const float* Wih1  = (const float*)d_in[5];
    const float* Whh1  = (const float*)d_in[6];
    const float* bih1  = (const float*)d_in[7];
    const float* bhh1  = (const float*)d_in[8];
    const float* Wih2  = (const float*)d_in[9];
    const float* Whh2  = (const float*)d_in[10];
    const float* bih2  = (const float*)d_in[11];
    const float* bhh2  = (const float*)d_in[12];
    const float* Wfc   = (const float*)d_in[13];
    const float* bfc   = (const float*)d_in[14];
    float* out = (float*)d_out;

    cudaFuncSetAttribute(lstm_fused_kernel,
                         cudaFuncAttributeMaxDynamicSharedMemorySize, FUSED_SMEM);

    zero_flags_kernel<<<3, 512>>>();
    lstm_fused_kernel<<<129, 256, FUSED_SMEM>>>(
        x, Wih0, Whh0, bih0, bhh0, Wih1, Whh1, bih1, bhh1,
        Wih2, Whh2, bih2, bhh2);
    fc_kernel<<<250, 256>>>(Wfc, bfc, out);
}

// round 15
// speedup vs baseline: 2.2047x; 1.4521x over previous
#include <cuda_runtime.h>
#include <cuda_bf16.h>
#include <cstdint>

// Problem: B=64, T=512, I=256, H=512, L=3, C=1000
#define NCLS  1000

// All activation tensors are stored tf32-rounded (f32 bit pattern, low mantissa
// zeroed) and k-pair-permuted within 8-blocks, so mma A-fragments are direct
// uint2 gmem loads.
// g_hh[layer][t][b][kperm(u)], g_xp[b][t][kperm(i)].

// ----------------- static device scratch -----------------
__device__ float g_hh[(size_t)3 * 512 * 64 * 512];   // 201 MB
__device__ float g_xp[(size_t)64 * 512 * 256];       // 32 MB  (permuted, rounded x)
__device__ int   g_flags[3 * 512];                   // per-layer per-step counters (43 arrivals)

// ----------------- helpers -----------------
__device__ __forceinline__ uint32_t f2tf(float x) {
    uint32_t u; asm("cvt.rna.tf32.f32 %0, %1;" : "=r"(u) : "f"(x)); return u;
}
// within each 8-block: logical k -> stored pos so stored pair (2p,2p+1) = logical (p, p+4)
__device__ __forceinline__ int kperm(int k) {
    return (k & ~7) | ((k & 3) << 1) | ((k >> 2) & 1);
}
__device__ __forceinline__ void mma_tf32(float* d, const uint32_t* a, const uint32_t* b) {
    asm volatile("mma.sync.aligned.m16n8k8.row.col.f32.tf32.tf32.f32 "
        "{%0,%1,%2,%3}, {%4,%5,%6,%7}, {%8,%9}, {%0,%1,%2,%3};"
        : "+f"(d[0]), "+f"(d[1]), "+f"(d[2]), "+f"(d[3])
        : "r"(a[0]), "r"(a[1]), "r"(a[2]), "r"(a[3]), "r"(b[0]), "r"(b[1]));
}
__device__ __forceinline__ float sigmoid_f(float x) {
    return 1.0f / (1.0f + __expf(-x));
}
__device__ __forceinline__ float tanh_f(float x) {
    float e = __expf(-2.0f * fabsf(x));
    float r = (1.0f - e) / (1.0f + e);
    return copysignf(r, x);
}
__device__ __forceinline__ void pollflag(const int* p, int target) {
    int v;
    asm volatile("ld.acquire.gpu.global.s32 %0, [%1];" : "=r"(v) : "l"(p));
    while (v < target) {
        __nanosleep(32);
        asm volatile("ld.acquire.gpu.global.s32 %0, [%1];" : "=r"(v) : "l"(p));
    }
}

// ----------------- prepass kernels -----------------
__global__ void zero_flags_kernel() {
    int i = blockIdx.x * blockDim.x + threadIdx.x;
    if (i < 3 * 512) g_flags[i] = 0;
}
// permute + tf32-round x: g_xp[(b*512+t)*256 + kperm(i)] = tf32(x[(b*512+t)*256 + i])
__global__ __launch_bounds__(256) void xperm_kernel(const float* __restrict__ x) {
    size_t idx = (size_t)blockIdx.x * 256 + threadIdx.x;   // 2,097,152 float4s
    float4 v = ((const float4*)x)[idx];
    int i0 = (int)((idx * 4) & 255);
    size_t base = (idx * 4) & ~(size_t)255;
    g_xp[base + kperm(i0 + 0)] = __uint_as_float(f2tf(v.x));
    g_xp[base + kperm(i0 + 1)] = __uint_as_float(f2tf(v.y));
    g_xp[base + kperm(i0 + 2)] = __uint_as_float(f2tf(v.z));
    g_xp[base + kperm(i0 + 3)] = __uint_as_float(f2tf(v.w));
}

// ----------------- fused 3-layer wavefront LSTM -----------------
// 129 CTAs (43/layer), 256 threads, all co-resident (1 CTA/SM, 129 <= 148 SMs).
// CTA (layer, lc) owns units [lc*12, +12) (last CTA: 8 real units; W rows
// zero-padded to 48 so all CTAs run one uniform path).
// Gate preact g = [cross | own] @ [W_ih | W_hh]^T + bias, where cross = x_t (L0,
// K=256) or h_{l-1}[t] (L1/2, K=512), own = h_l[t-1] (K=512).
// W slice (48 x K tf32, k-permuted) SMEM-resident for all 512 steps.
// 8 warps = 4 m-groups (16 batches) x 2 k-halves; per warp: m16 x n48 x K/2.
// A-fragments load straight from gmem (__ldcg uint2, 8-deep k8 ring); B from SMEM.
// k-half partials in gbuf[2]; elementwise sums both + bias.
// Flags: layer l step t waits flag[l-1][t] (l>0) and flag[l][t-1] (t>0);
// arrives on flag[l][t] via red.release.gpu after writing h.
#define RWMAX 1028
#define FUSED_SMEM ((48 * RWMAX + 2 * 64 * 50 + 48) * 4)   // 223,168 B

__global__ __launch_bounds__(256, 1) void lstm_fused_kernel(
    const float* __restrict__ Wih0, const float* __restrict__ Whh0,
    const float* __restrict__ bih0, const float* __restrict__ bhh0,
    const float* __restrict__ Wih1, const float* __restrict__ Whh1,
    const float* __restrict__ bih1, const float* __restrict__ bhh1,
    const float* __restrict__ Wih2, const float* __restrict__ Whh2,
    const float* __restrict__ bih2, const float* __restrict__ bhh2)
{
    extern __shared__ uint32_t sm[];
    uint32_t* W_s    = sm;                                   // 48 x RWS (<= RWMAX)
    float*    gbuf0  = (float*)(sm + 48 * RWMAX);            // 64 x 50
    float*    gbuf1  = gbuf0 + 64 * 50;                      // 64 x 50
    float*    bias_s = gbuf1 + 64 * 50;                      // 48

    const int tid   = threadIdx.x;
    const int bid   = blockIdx.x;
    const int layer = bid / 43, lc = bid % 43;
    const int nu    = (lc == 42) ? 8 : 12;                   // real units
    const int u0    = lc * 12;
    const int KX    = (layer == 0) ? 256 : 512;
    const int RWS   = KX + 512 + 4;                          // 772 or 1028

    const float* Wcross = (layer == 0) ? Wih0 : ((layer == 1) ? Wih1 : Wih2);
    const float* Wown   = (layer == 0) ? Whh0 : ((layer == 1) ? Whh1 : Whh2);
    const float* bA     = (layer == 0) ? bih0 : ((layer == 1) ? bih1 : bih2);
    const float* bB     = (layer == 0) ? bhh0 : ((layer == 1) ? bhh1 : bhh2);

    const int w = tid >> 5, lane = tid & 31;
    const int grp = lane >> 2, tig = lane & 3;
    const int wm = w & 3, kh = w >> 2;                       // m-group, k-half
    const int bm0 = wm * 16;

    // ---- init: W slice (k-permuted tf32; pad rows with jm >= nu to 0) ----
    for (int n = 0; n < 48; ++n) {
        int q = n / 12, jm = n % 12;
        bool valid = jm < nu;
        int gr = q * 512 + u0 + jm;
        for (int k = tid; k < KX + 512; k += 256) {
            uint32_t wv = 0;
            if (valid) {
                if (k < KX) wv = f2tf(Wcross[(size_t)gr * KX + k]);
                else        wv = f2tf(Wown[(size_t)gr * 512 + (k - KX)]);
            }
            int kk = (k < KX) ? kperm(k) : (KX + kperm(k - KX));
            W_s[n * RWS + kk] = wv;
        }
    }
    if (tid < 48) {
        int q = tid / 12, jm = tid % 12;
        bias_s[tid] = (jm < nu) ? (bA[q * 512 + u0 + jm] + bB[q * 512 + u0 + jm]) : 0.f;
    }
    __syncthreads();

    float acc[6][4];
    float cst[3] = {0.f, 0.f, 0.f};

    // per-segment mma: A-frags direct from gmem (uint2, 8-deep k8 ring), B from W_s.
    // Ab: base of A segment (column 0 of this segment, batch row 0);
    // rstride: floats per batch row; wc: W_s column offset; nk8: # of k8 steps.
    auto runseg = [&](const float* Ab, size_t rstride, int wc, int nk8) {
        const uint2* p0 = (const uint2*)(Ab + (size_t)(bm0 + grp) * rstride) + tig;
        const uint2* p1 = (const uint2*)(Ab + (size_t)(bm0 + grp + 8) * rstride) + tig;
        uint2 a0[8], a1[8];
        #pragma unroll
        for (int u = 0; u < 8; ++u) { a0[u] = __ldcg(p0 + u * 4); a1[u] = __ldcg(p1 + u * 4); }
        for (int ki = 0; ki < nk8; ki += 8) {
            #pragma unroll
            for (int u = 0; u < 8; ++u) {
                uint2 lo = a0[u], hi = a1[u];
                if (ki + u + 8 < nk8) {
                    a0[u] = __ldcg(p0 + (ki + u + 8) * 4);
                    a1[u] = __ldcg(p1 + (ki + u + 8) * 4);
                }
                uint32_t Af[4] = {lo.x, hi.x, lo.y, hi.y};
                const uint32_t* wp = W_s + grp * RWS + wc + (ki + u) * 8 + 2 * tig;
                #pragma unroll
                for (int nf = 0; nf < 6; ++nf) {
                    uint2 bb = *(const uint2*)(wp + nf * 8 * RWS);
                    uint32_t Bf[2] = {bb.x, bb.y};
                    mma_tf32(acc[nf], Af, Bf);
                }
            }
        }
    };

    for (int t = 0; t < 512; ++t) {
        if (layer > 0 && tid == 0) pollflag(&g_flags[(layer - 1) * 512 + t], 43);
        if (t > 0 && tid == 32)    pollflag(&g_flags[layer * 512 + t - 1], 43);
        __syncthreads();

        #pragma unroll
        for (int nf = 0; nf < 6; ++nf)
            #pragma unroll
            for (int r = 0; r < 4; ++r) acc[nf][r] = 0.f;

        const float* hown = g_hh + (((size_t)layer * 512 + (t - 1)) * 64) * 512;
        if (kh == 0) {
            if (layer == 0) {
                // x segment: W cols [0,256), A = g_xp rows (stride 512*256)
                runseg(g_xp + (size_t)t * 256, 131072, 0, 32);
                // own-h first quarter: W cols [256,384) <-> h cols [0,128)
                if (t > 0) runseg(hown, 512, 256, 16);
            } else {
                // cross-h: W cols [0,512) <-> h_{l-1}[t] cols [0,512)
                const float* hx = g_hh + (((size_t)(layer - 1) * 512 + t) * 64) * 512;
                runseg(hx, 512, 0, 64);
            }
        } else if (t > 0) {
            if (layer == 0) {
                // own-h remainder: W cols [384,768) <-> h cols [128,512)
                runseg(hown + 128, 512, 384, 48);
            } else {
                // own-h full: W cols [512,1024) <-> h cols [0,512)   (A col offset 0!)
                runseg(hown, 512, 512, 64);
            }
        }

        // gate partials -> gbuf[kh]
        float* gb = kh ? gbuf1 : gbuf0;
        #pragma unroll
        for (int nf = 0; nf < 6; ++nf) {
            int col = nf * 8 + 2 * tig;
            *(float2*)&gb[(bm0 + grp) * 50 + col] = make_float2(acc[nf][0], acc[nf][1]);
            *(float2*)&gb[(bm0 + grp + 8) * 50 + col] = make_float2(acc[nf][2], acc[nf][3]);
        }
        __syncthreads();

        // elementwise: slot e = (b, j) over 64 x 12 padded; store only j < nu
        #pragma unroll
        for (int i = 0; i < 3; ++i) {
            int e = i * 256 + tid;
            int b = e & 63, j = e >> 6;
            float gi = gbuf0[b * 50 + 0 * 12 + j] + gbuf1[b * 50 + 0 * 12 + j] + bias_s[0 * 12 + j];
            float gf = gbuf0[b * 50 + 1 * 12 + j] + gbuf1[b * 50 + 1 * 12 + j] + bias_s[1 * 12 + j];
            float gg = gbuf0[b * 50 + 2 * 12 + j] + gbuf1[b * 50 + 2 * 12 + j] + bias_s[2 * 12 + j];
            float go = gbuf0[b * 50 + 3 * 12 + j] + gbuf1[b * 50 + 3 * 12 + j] + bias_s[3 * 12 + j];
            float iv = sigmoid_f(gi), fv = sigmoid_f(gf), ov = sigmoid_f(go);
            float gt = tanh_f(gg);
            cst[i] = fv * cst[i] + iv * gt;
            float hv = ov * tanh_f(cst[i]);
            if (j < nu) {
                g_hh[(((size_t)layer * 512 + t) * 64 + b) * 512 + kperm(u0 + j)] =
                    __uint_as_float(f2tf(hv));
            }
        }

        __syncthreads();
        if (tid == 0)
            asm volatile("red.release.gpu.global.add.s32 [%0], %1;"
                         :: "l"(g_flags + layer * 512 + t), "r"(1) : "memory");
    }
}

// ----------------- FC head: out[64,1000] = h2[511] @ W_fc^T + b_fc -----------------
// h2 stored k-permuted -> load W_fc with the same permutation.
__global__ __launch_bounds__(256) void fc_kernel(
    const float* __restrict__ Wfc, const float* __restrict__ bfc, float* __restrict__ out)
{
    __shared__ __align__(16) float Ws[4 * 512];
    const int tid = threadIdx.x;
    const int c0 = blockIdx.x * 4;

    for (int i = tid; i < 2048; i += 256) {
        int cc = i >> 9, k = i & 511;
        Ws[cc * 512 + kperm(k)] = (c0 + cc < NCLS) ? Wfc[(size_t)(c0 + cc) * 512 + k] : 0.f;
    }
    __syncthreads();

    int b = tid & 63, ci = tid >> 6;
    int c = c0 + ci;
    if (c < NCLS) {
        const float4* hvp = (const float4*)(g_hh + (((size_t)2 * 512 + 511) * 64 + b) * 512);
        const float4* wvp = (const float4*)(Ws + ci * 512);
        float acc = 0.f;
        #pragma unroll 8
        for (int k = 0; k < 128; ++k) {
            float4 h4 = hvp[k], w4 = wvp[k];
            acc += h4.x * w4.x + h4.y * w4.y + h4.z * w4.z + h4.w * w4.w;
        }
        out[b * NCLS + c] = acc + bfc[c];
    }
}

// ----------------- launch -----------------
extern "C" void kernel_launch(void* const* d_in, const int* in_sizes, int n_in,
                              void* d_out, int out_size)
{
    const float* x     = (const float*)d_in[0];
    const float* Wih0  = (const float*)d_in[1];
    const float* Whh0  = (const float*)d_in[2];
    const float* bih0  = (const float*)d_in[3];
    const float* bhh0  = (const float*)d_in[4];
    const float* Wih1  = (const float*)d_in[5];
    const float* Whh1  = (const float*)d_in[6];
    const float* bih1  = (const float*)d_in[7];
    const float* bhh1  = (const float*)d_in[8];
    const float* Wih2  = (const float*)d_in[9];
    const float* Whh2  = (const float*)d_in[10];
    const float* bih2  = (const float*)d_in[11];
    const float* bhh2  = (const float*)d_in[12];
    const float* Wfc   = (const float*)d_in[13];
    const float* bfc   = (const float*)d_in[14];
    float* out = (float*)d_out;

    cudaFuncSetAttribute(lstm_fused_kernel,
                         cudaFuncAttributeMaxDynamicSharedMemorySize, FUSED_SMEM);

    zero_flags_kernel<<<3, 512>>>();
    xperm_kernel<<<8192, 256>>>(x);
    lstm_fused_kernel<<<129, 256, FUSED_SMEM>>>(
        Wih0, Whh0, bih0, bhh0, Wih1, Whh1, bih1, bhh1,
        Wih2, Whh2, bih2, bhh2);
    fc_kernel<<<250, 256>>>(Wfc, bfc, out);
}

// round 16
// speedup vs baseline: 2.7615x; 1.2526x over previous
#include <cuda_runtime.h>
#include <cuda_bf16.h>
#include <cstdint>

// Problem: B=64, T=512, I=256, H=512, L=3, C=1000
#define NCLS  1000

// All activation tensors are stored tf32-rounded (f32 bit pattern, low mantissa
// zeroed) and k-pair-permuted within 8-blocks, so mma A-fragments are direct
// uint2 gmem loads.  g_hh[layer][t][b][kperm(u)], g_xp[b][t][kperm(i)].

// ----------------- static device scratch -----------------
__device__ float g_hh[(size_t)3 * 512 * 64 * 512];   // 201 MB
__device__ float g_xp[(size_t)64 * 512 * 256];       // 32 MB  (permuted, rounded x)
__device__ int   g_flags[3 * 512];                   // per-layer per-step counters (43 arrivals)

// ----------------- helpers -----------------
__device__ __forceinline__ uint32_t f2tf(float x) {
    uint32_t u; asm("cvt.rna.tf32.f32 %0, %1;" : "=r"(u) : "f"(x)); return u;
}
// within each 8-block: logical k -> stored pos so stored pair (2p,2p+1) = logical (p, p+4)
__device__ __forceinline__ int kperm(int k) {
    return (k & ~7) | ((k & 3) << 1) | ((k >> 2) & 1);
}
__device__ __forceinline__ void mma_tf32(float* d, const uint32_t* a, const uint32_t* b) {
    asm volatile("mma.sync.aligned.m16n8k8.row.col.f32.tf32.tf32.f32 "
        "{%0,%1,%2,%3}, {%4,%5,%6,%7}, {%8,%9}, {%0,%1,%2,%3};"
        : "+f"(d[0]), "+f"(d[1]), "+f"(d[2]), "+f"(d[3])
        : "r"(a[0]), "r"(a[1]), "r"(a[2]), "r"(a[3]), "r"(b[0]), "r"(b[1]));
}
__device__ __forceinline__ float sigmoid_f(float x) {
    return 1.0f / (1.0f + __expf(-x));
}
__device__ __forceinline__ float tanh_f(float x) {
    float e = __expf(-2.0f * fabsf(x));
    float r = (1.0f - e) / (1.0f + e);
    return copysignf(r, x);
}
// all lanes poll (coalesces to one sector); acquire gives the h-visibility edge
__device__ __forceinline__ void pollflag(const int* p, int target) {
    int v;
    asm volatile("ld.acquire.gpu.global.s32 %0, [%1];" : "=r"(v) : "l"(p));
    while (v < target) {
        __nanosleep(32);
        asm volatile("ld.acquire.gpu.global.s32 %0, [%1];" : "=r"(v) : "l"(p));
    }
}

// ----------------- prepass kernels -----------------
__global__ void zero_flags_kernel() {
    int i = blockIdx.x * blockDim.x + threadIdx.x;
    if (i < 3 * 512) g_flags[i] = 0;
}
__global__ __launch_bounds__(256) void xperm_kernel(const float* __restrict__ x) {
    size_t idx = (size_t)blockIdx.x * 256 + threadIdx.x;   // 2,097,152 float4s
    float4 v = ((const float4*)x)[idx];
    int i0 = (int)((idx * 4) & 255);
    size_t base = (idx * 4) & ~(size_t)255;
    g_xp[base + kperm(i0 + 0)] = __uint_as_float(f2tf(v.x));
    g_xp[base + kperm(i0 + 1)] = __uint_as_float(f2tf(v.y));
    g_xp[base + kperm(i0 + 2)] = __uint_as_float(f2tf(v.z));
    g_xp[base + kperm(i0 + 3)] = __uint_as_float(f2tf(v.w));
}

// ----------------- fused 3-layer wavefront LSTM -----------------
// 129 CTAs (43/layer), 256 threads, co-resident (1 CTA/SM). CTA (layer, lc)
// owns units [lc*12,+12) (last CTA: 8 real; W rows zero-padded to 48).
// 8 warps, warp w: seg = w>>2 (0 = own-recurrence, 1 = cross-input),
// kh = w&1 (k-half), mh = (w>>1)&1 (m-half, 32 batches). Each SMSP hosts one
// own + one cross warp, so cross work overlaps the own serial chain.
// Own warps wait flag[l][t-1]; cross warps wait flag[l-1][t] (L0: none).
// Warp tile m32 x n48 x K/2; A-frags direct from gmem (__ldcg uint2, 4-deep ring);
// B from SMEM-resident W slice. kh partials combined via named bar + RMW.
#define RWMAX 1028
#define FUSED_SMEM ((48 * RWMAX + 2 * 64 * 50 + 48) * 4)   // 223,168 B

__global__ __launch_bounds__(256, 1) void lstm_fused_kernel(
    const float* __restrict__ Wih0, const float* __restrict__ Whh0,
    const float* __restrict__ bih0, const float* __restrict__ bhh0,
    const float* __restrict__ Wih1, const float* __restrict__ Whh1,
    const float* __restrict__ bih1, const float* __restrict__ bhh1,
    const float* __restrict__ Wih2, const float* __restrict__ Whh2,
    const float* __restrict__ bih2, const float* __restrict__ bhh2)
{
    extern __shared__ uint32_t sm[];
    uint32_t* W_s    = sm;                                   // 48 x RWS (<= RWMAX)
    float*    gbufC  = (float*)(sm + 48 * RWMAX);            // cross partials 64 x 50
    float*    gbufO  = gbufC + 64 * 50;                      // own partials   64 x 50
    float*    bias_s = gbufO + 64 * 50;                      // 48

    const int tid   = threadIdx.x;
    const int bid   = blockIdx.x;
    const int layer = bid / 43, lc = bid % 43;
    const int nu    = (lc == 42) ? 8 : 12;
    const int u0    = lc * 12;
    const int KX    = (layer == 0) ? 256 : 512;              // cross K
    const int RWS   = KX + 512 + 4;                          // 772 or 1028

    const float* Wcross = (layer == 0) ? Wih0 : ((layer == 1) ? Wih1 : Wih2);
    const float* Wown   = (layer == 0) ? Whh0 : ((layer == 1) ? Whh1 : Whh2);
    const float* bA     = (layer == 0) ? bih0 : ((layer == 1) ? bih1 : bih2);
    const float* bB     = (layer == 0) ? bhh0 : ((layer == 1) ? bhh1 : bhh2);

    const int w = tid >> 5, lane = tid & 31;
    const int grp = lane >> 2, tig = lane & 3;
    const int seg = w >> 2;                                  // 0=own 1=cross
    const int kh  = w & 1, mh = (w >> 1) & 1;
    const int bm0 = mh * 32;
    const int barid = 1 + (w >> 1);                          // kh-pair named bar (64 thr)

    // ---- init: W slice (k-permuted tf32; rows jm >= nu zero) + bias ----
    for (int n = 0; n < 48; ++n) {
        int q = n / 12, jm = n % 12;
        bool valid = jm < nu;
        int gr = q * 512 + u0 + jm;
        for (int k = tid; k < KX + 512; k += 256) {
            uint32_t wv = 0;
            if (valid) {
                if (k < KX) wv = f2tf(Wcross[(size_t)gr * KX + k]);
                else        wv = f2tf(Wown[(size_t)gr * 512 + (k - KX)]);
            }
            int kk = (k < KX) ? kperm(k) : (KX + kperm(k - KX));
            W_s[n * RWS + kk] = wv;
        }
    }
    if (tid < 48) {
        int q = tid / 12, jm = tid % 12;
        bias_s[tid] = (jm < nu) ? (bA[q * 512 + u0 + jm] + bB[q * 512 + u0 + jm]) : 0.f;
    }
    __syncthreads();

    float acc[2][6][4];
    float cst[3] = {0.f, 0.f, 0.f};

    // m32 x n48 segment: A from gmem (4-deep k8 ring, 4 row-pointers), B from W_s.
    auto runseg = [&](const float* Ab, size_t rstride, int wc, int nk8) {
        const uint2* p0 = (const uint2*)(Ab + (size_t)(bm0 + grp)      * rstride) + tig;
        const uint2* p1 = (const uint2*)(Ab + (size_t)(bm0 + grp + 8)  * rstride) + tig;
        const uint2* p2 = (const uint2*)(Ab + (size_t)(bm0 + grp + 16) * rstride) + tig;
        const uint2* p3 = (const uint2*)(Ab + (size_t)(bm0 + grp + 24) * rstride) + tig;
        uint2 a0[4], a1[4], a2[4], a3[4];
        #pragma unroll
        for (int d = 0; d < 4; ++d) {
            a0[d] = __ldcg(p0 + d * 4); a1[d] = __ldcg(p1 + d * 4);
            a2[d] = __ldcg(p2 + d * 4); a3[d] = __ldcg(p3 + d * 4);
        }
        for (int ki = 0; ki < nk8; ki += 4) {
            #pragma unroll
            for (int u = 0; u < 4; ++u) {
                uint2 v0 = a0[u], v1 = a1[u], v2 = a2[u], v3 = a3[u];
                if (ki + u + 4 < nk8) {
                    a0[u] = __ldcg(p0 + (ki + u + 4) * 4);
                    a1[u] = __ldcg(p1 + (ki + u + 4) * 4);
                    a2[u] = __ldcg(p2 + (ki + u + 4) * 4);
                    a3[u] = __ldcg(p3 + (ki + u + 4) * 4);
                }
                uint32_t Af0[4] = {v0.x, v1.x, v0.y, v1.y};
                uint32_t Af1[4] = {v2.x, v3.x, v2.y, v3.y};
                const uint32_t* wp = W_s + grp * RWS + wc + (ki + u) * 8 + 2 * tig;
                #pragma unroll
                for (int nf = 0; nf < 6; ++nf) {
                    uint2 bb = *(const uint2*)(wp + nf * 8 * RWS);
                    uint32_t Bf[2] = {bb.x, bb.y};
                    mma_tf32(acc[0][nf], Af0, Bf);
                    mma_tf32(acc[1][nf], Af1, Bf);
                }
            }
        }
    };

    auto zeroacc = [&]() {
        #pragma unroll
        for (int mf = 0; mf < 2; ++mf)
            #pragma unroll
            for (int nf = 0; nf < 6; ++nf)
                #pragma unroll
                for (int r = 0; r < 4; ++r) acc[mf][nf][r] = 0.f;
    };
    // kh0 writes its m32 rows; named bar; kh1 adds.
    auto combine = [&](float* gb) {
        if (kh == 0) {
            #pragma unroll
            for (int mf = 0; mf < 2; ++mf)
                #pragma unroll
                for (int nf = 0; nf < 6; ++nf) {
                    int m = bm0 + mf * 16 + grp, col = nf * 8 + 2 * tig;
                    *(float2*)&gb[m * 50 + col] = make_float2(acc[mf][nf][0], acc[mf][nf][1]);
                    *(float2*)&gb[(m + 8) * 50 + col] = make_float2(acc[mf][nf][2], acc[mf][nf][3]);
                }
        }
        asm volatile("bar.sync %0, 64;" :: "r"(barid) : "memory");
        if (kh == 1) {
            #pragma unroll
            for (int mf = 0; mf < 2; ++mf)
                #pragma unroll
                for (int nf = 0; nf < 6; ++nf) {
                    int m = bm0 + mf * 16 + grp, col = nf * 8 + 2 * tig;
                    float2 q0 = *(float2*)&gb[m * 50 + col];
                    float2 q1 = *(float2*)&gb[(m + 8) * 50 + col];
                    q0.x += acc[mf][nf][0]; q0.y += acc[mf][nf][1];
                    q1.x += acc[mf][nf][2]; q1.y += acc[mf][nf][3];
                    *(float2*)&gb[m * 50 + col] = q0;
                    *(float2*)&gb[(m + 8) * 50 + col] = q1;
                }
        }
    };

    for (int t = 0; t < 512; ++t) {
        zeroacc();
        if (seg == 1) {
            // ---- cross segment (off the intra-layer chain) ----
            if (layer == 0) {
                // x: K=256, kh halves of 128 cols each
                runseg(g_xp + (size_t)t * 256 + kh * 128, 131072, kh * 128, 16);
            } else {
                pollflag(&g_flags[(layer - 1) * 512 + t], 43);
                const float* hx = g_hh + (((size_t)(layer - 1) * 512 + t) * 64) * 512;
                runseg(hx + kh * 256, 512, kh * 256, 32);
            }
            combine(gbufC);
        } else {
            // ---- own segment (serial chain): W cols [KX, KX+512) ----
            if (t > 0) {
                pollflag(&g_flags[layer * 512 + t - 1], 43);
                const float* hown = g_hh + (((size_t)layer * 512 + (t - 1)) * 64) * 512;
                runseg(hown + kh * 256, 512, KX + kh * 256, 32);
            }
            combine(gbufO);
        }
        __syncthreads();

        // ---- elementwise: slot e = (b, j) over 64 x 12 padded ----
        #pragma unroll
        for (int i = 0; i < 3; ++i) {
            int e = i * 256 + tid;
            int b = e & 63, j = e >> 6;
            float gi = gbufC[b * 50 + 0 * 12 + j] + gbufO[b * 50 + 0 * 12 + j] + bias_s[0 * 12 + j];
            float gf = gbufC[b * 50 + 1 * 12 + j] + gbufO[b * 50 + 1 * 12 + j] + bias_s[1 * 12 + j];
            float gg = gbufC[b * 50 + 2 * 12 + j] + gbufO[b * 50 + 2 * 12 + j] + bias_s[2 * 12 + j];
            float go = gbufC[b * 50 + 3 * 12 + j] + gbufO[b * 50 + 3 * 12 + j] + bias_s[3 * 12 + j];
            float iv = sigmoid_f(gi), fv = sigmoid_f(gf), ov = sigmoid_f(go);
            float gt = tanh_f(gg);
            cst[i] = fv * cst[i] + iv * gt;
            float hv = ov * tanh_f(cst[i]);
            if (j < nu) {
                g_hh[(((size_t)layer * 512 + t) * 64 + b) * 512 + kperm(u0 + j)] =
                    __uint_as_float(f2tf(hv));
            }
        }

        __syncthreads();
        if (tid == 0)
            asm volatile("red.release.gpu.global.add.s32 [%0], %1;"
                         :: "l"(g_flags + layer * 512 + t), "r"(1) : "memory");
    }
}

// ----------------- FC head: out[64,1000] = h2[511] @ W_fc^T + b_fc -----------------
__global__ __launch_bounds__(256) void fc_kernel(
    const float* __restrict__ Wfc, const float* __restrict__ bfc, float* __restrict__ out)
{
    __shared__ __align__(16) float Ws[4 * 512];
    const int tid = threadIdx.x;
    const int c0 = blockIdx.x * 4;

    for (int i = tid; i < 2048; i += 256) {
        int cc = i >> 9, k = i & 511;
        Ws[cc * 512 + kperm(k)] = (c0 + cc < NCLS) ? Wfc[(size_t)(c0 + cc) * 512 + k] : 0.f;
    }
    __syncthreads();

    int b = tid & 63, ci = tid >> 6;
    int c = c0 + ci;
    if (c < NCLS) {
        const float4* hvp = (const float4*)(g_hh + (((size_t)2 * 512 + 511) * 64 + b) * 512);
        const float4* wvp = (const float4*)(Ws + ci * 512);
        float acc = 0.f;
        #pragma unroll 8
        for (int k = 0; k < 128; ++k) {
            float4 h4 = hvp[k], w4 = wvp[k];
            acc += h4.x * w4.x + h4.y * w4.y + h4.z * w4.z + h4.w * w4.w;
        }
        out[b * NCLS + c] = acc + bfc[c];
    }
}

// ----------------- launch -----------------
extern "C" void kernel_launch(void* const* d_in, const int* in_sizes, int n_in,
                              void* d_out, int out_size)
{
    const float* x     = (const float*)d_in[0];
    const float* Wih0  = (const float*)d_in[1];
    const float* Whh0  = (const float*)d_in[2];
    const float* bih0  = (const float*)d_in[3];
    const float* bhh0  = (const float*)d_in[4];
    const float* Wih1  = (const float*)d_in[5];
    const float* Whh1  = (const float*)d_in[6];
    const float* bih1  = (const float*)d_in[7];
    const float* bhh1  = (const float*)d_in[8];
    const float* Wih2  = (const float*)d_in[9];
    const float* Whh2  = (const float*)d_in[10];
    const float* bih2  = (const float*)d_in[11];
    const float* bhh2  = (const float*)d_in[12];
    const float* Wfc   = (const float*)d_in[13];
    const float* bfc   = (const float*)d_in[14];
    float* out = (float*)d_out;

    cudaFuncSetAttribute(lstm_fused_kernel,
                         cudaFuncAttributeMaxDynamicSharedMemorySize, FUSED_SMEM);

    zero_flags_kernel<<<3, 512>>>();
    xperm_kernel<<<8192, 256>>>(x);
    lstm_fused_kernel<<<129, 256, FUSED_SMEM>>>(
        Wih0, Whh0, bih0, bhh0, Wih1, Whh1, bih1, bhh1,
        Wih2, Whh2, bih2, bhh2);
    fc_kernel<<<250, 256>>>(Wfc, bfc, out);
}

// round 17
// speedup vs baseline: 4.3473x; 1.5743x over previous
#include <cuda_runtime.h>
#include <cuda_fp16.h>
#include <cstdint>

// Problem: B=64, T=512, I=256, H=512, L=3, C=1000
#define NCLS  1000

// Activations stored as fp16, permuted within 16-blocks by kperm16 so that one
// uint2 (4 halves) per row per k16 step is exactly one mma.m16n8k16 fragment
// row-pair: stored [4p..4p+3] = logical {2p, 2p+1, 2p+8, 2p+9}.
// g_hh[layer][t][b][kperm16(u)], g_xp[b][t][kperm16(i)].

// ----------------- static device scratch -----------------
__device__ __half g_hh[(size_t)3 * 512 * 64 * 512];   // 100 MB
__device__ __half g_xp[(size_t)64 * 512 * 256];       // 16 MB
__device__ int    g_flags[3 * 512];                   // per-layer per-step counters (43 arrivals)

// ----------------- helpers -----------------
__device__ __host__ __forceinline__ int kperm16(int k) {
    // within each 16-block: pos = 4*((k&7)>>1) + 2*((k>>3)&1) + (k&1)
    return (k & ~15) | (((k & 7) >> 1) << 2) | (((k >> 3) & 1) << 1) | (k & 1);
}
__device__ __forceinline__ void mma_f16(float* d, const uint32_t* a, const uint32_t* b) {
    asm volatile("mma.sync.aligned.m16n8k16.row.col.f32.f16.f16.f32 "
        "{%0,%1,%2,%3}, {%4,%5,%6,%7}, {%8,%9}, {%0,%1,%2,%3};"
        : "+f"(d[0]), "+f"(d[1]), "+f"(d[2]), "+f"(d[3])
        : "r"(a[0]), "r"(a[1]), "r"(a[2]), "r"(a[3]), "r"(b[0]), "r"(b[1]));
}
__device__ __forceinline__ float sigmoid_f(float x) {
    return 1.0f / (1.0f + __expf(-x));
}
__device__ __forceinline__ float tanh_f(float x) {
    float e = __expf(-2.0f * fabsf(x));
    float r = (1.0f - e) / (1.0f + e);
    return copysignf(r, x);
}
__device__ __forceinline__ void pollflag(const int* p, int target) {
    int v;
    asm volatile("ld.acquire.gpu.global.s32 %0, [%1];" : "=r"(v) : "l"(p));
    while (v < target) {
        __nanosleep(32);
        asm volatile("ld.acquire.gpu.global.s32 %0, [%1];" : "=r"(v) : "l"(p));
    }
}

// ----------------- prepass kernels -----------------
__global__ void zero_flags_kernel() {
    int i = blockIdx.x * blockDim.x + threadIdx.x;
    if (i < 3 * 512) g_flags[i] = 0;
}
__global__ __launch_bounds__(256) void xperm_kernel(const float* __restrict__ x) {
    size_t idx = (size_t)blockIdx.x * 256 + threadIdx.x;   // 2,097,152 float4s
    float4 v = ((const float4*)x)[idx];
    int i0 = (int)((idx * 4) & 255);
    size_t base = (idx * 4) & ~(size_t)255;
    g_xp[base + kperm16(i0 + 0)] = __float2half_rn(v.x);
    g_xp[base + kperm16(i0 + 1)] = __float2half_rn(v.y);
    g_xp[base + kperm16(i0 + 2)] = __float2half_rn(v.z);
    g_xp[base + kperm16(i0 + 3)] = __float2half_rn(v.w);
}

// ----------------- fused 3-layer wavefront LSTM -----------------
// 129 CTAs (43/layer), 256 threads, co-resident (1 CTA/SM). CTA (layer, lc)
// owns units [lc*12,+12) (last CTA: 8 real; W rows zero-padded to 48).
// 8 warps, warp w: seg = w>>2 (0 = own-recurrence, 1 = cross-input),
// kh = w&1 (k-half), mh = (w>>1)&1 (m-half, 32 batches). Each SMSP hosts one
// own + one cross warp, so cross work overlaps the own serial chain.
// Own warps wait flag[l][t-1]; cross warps wait flag[l-1][t] (L0: none).
// Warp tile m32 x n48 x K/2 via fp16 mma.m16n8k16; A-frags direct from gmem
// (__ldcg uint2, 4-deep k16 ring); B from SMEM-resident fp16 W slice.
#define RWS_MAXH 1032                                  // W_s row stride (halves)
#define FUSED_SMEM ((24 * RWS_MAXH + 2 * 64 * 50 + 48) * 4)   // 124,160 B

__global__ __launch_bounds__(256, 1) void lstm_fused_kernel(
    const float* __restrict__ Wih0, const float* __restrict__ Whh0,
    const float* __restrict__ bih0, const float* __restrict__ bhh0,
    const float* __restrict__ Wih1, const float* __restrict__ Whh1,
    const float* __restrict__ bih1, const float* __restrict__ bhh1,
    const float* __restrict__ Wih2, const float* __restrict__ Whh2,
    const float* __restrict__ bih2, const float* __restrict__ bhh2)
{
    extern __shared__ uint32_t sm[];
    __half* W_s    = (__half*)sm;                        // 48 x RWS_H halves
    float*  gbufC  = (float*)(sm + 24 * RWS_MAXH);       // cross partials 64 x 50
    float*  gbufO  = gbufC + 64 * 50;                    // own partials   64 x 50
    float*  bias_s = gbufO + 64 * 50;                    // 48

    const int tid   = threadIdx.x;
    const int bid   = blockIdx.x;
    const int layer = bid / 43, lc = bid % 43;
    const int nu    = (lc == 42) ? 8 : 12;
    const int u0    = lc * 12;
    const int KX    = (layer == 0) ? 256 : 512;          // cross K
    const int RWS_H = KX + 512 + 8;                      // 776 or 1032 (mult of 8)

    const float* Wcross = (layer == 0) ? Wih0 : ((layer == 1) ? Wih1 : Wih2);
    const float* Wown   = (layer == 0) ? Whh0 : ((layer == 1) ? Whh1 : Whh2);
    const float* bA     = (layer == 0) ? bih0 : ((layer == 1) ? bih1 : bih2);
    const float* bB     = (layer == 0) ? bhh0 : ((layer == 1) ? bhh1 : bhh2);

    const int w = tid >> 5, lane = tid & 31;
    const int grp = lane >> 2, tig = lane & 3;
    const int seg = w >> 2;                              // 0=own 1=cross
    const int kh  = w & 1, mh = (w >> 1) & 1;
    const int bm0 = mh * 32;
    const int barid = 1 + (w >> 1);                      // kh-pair named bar (64 thr)

    // ---- init: W slice (fp16, kperm16; rows jm >= nu zero) + bias ----
    for (int n = 0; n < 48; ++n) {
        int q = n / 12, jm = n % 12;
        bool valid = jm < nu;
        int gr = q * 512 + u0 + jm;
        for (int k = tid; k < KX + 512; k += 256) {
            float wv = 0.f;
            if (valid) {
                if (k < KX) wv = Wcross[(size_t)gr * KX + k];
                else        wv = Wown[(size_t)gr * 512 + (k - KX)];
            }
            int kk = (k < KX) ? kperm16(k) : (KX + kperm16(k - KX));
            W_s[n * RWS_H + kk] = __float2half_rn(wv);
        }
    }
    if (tid < 48) {
        int q = tid / 12, jm = tid % 12;
        bias_s[tid] = (jm < nu) ? (bA[q * 512 + u0 + jm] + bB[q * 512 + u0 + jm]) : 0.f;
    }
    __syncthreads();

    float acc[2][6][4];
    float cst[2][2] = {{0.f, 0.f}, {0.f, 0.f}};          // 2 slots x 2 units

    // m32 x n48 x (nk16*16) segment: A from gmem (4-deep k16 ring), B from W_s.
    // Ab: A segment base (halves); rstride in halves; wc: W_s col offset (halves).
    auto runseg = [&](const __half* Ab, size_t rstride, int wc, int nk16) {
        const uint2* p0 = (const uint2*)(Ab + (size_t)(bm0 + grp)      * rstride) + tig;
        const uint2* p1 = (const uint2*)(Ab + (size_t)(bm0 + grp + 8)  * rstride) + tig;
        const uint2* p2 = (const uint2*)(Ab + (size_t)(bm0 + grp + 16) * rstride) + tig;
        const uint2* p3 = (const uint2*)(Ab + (size_t)(bm0 + grp + 24) * rstride) + tig;
        uint2 a0[4], a1[4], a2[4], a3[4];
        #pragma unroll
        for (int d = 0; d < 4; ++d) {
            a0[d] = __ldcg(p0 + d * 4); a1[d] = __ldcg(p1 + d * 4);
            a2[d] = __ldcg(p2 + d * 4); a3[d] = __ldcg(p3 + d * 4);
        }
        for (int ki = 0; ki < nk16; ki += 4) {
            #pragma unroll
            for (int u = 0; u < 4; ++u) {
                uint2 v0 = a0[u], v1 = a1[u], v2 = a2[u], v3 = a3[u];
                if (ki + u + 4 < nk16) {
                    a0[u] = __ldcg(p0 + (ki + u + 4) * 4);
                    a1[u] = __ldcg(p1 + (ki + u + 4) * 4);
                    a2[u] = __ldcg(p2 + (ki + u + 4) * 4);
                    a3[u] = __ldcg(p3 + (ki + u + 4) * 4);
                }
                // fragment: {row lo-pair, row+8 lo-pair, row hi-pair, row+8 hi-pair}
                uint32_t Af0[4] = {v0.x, v1.x, v0.y, v1.y};
                uint32_t Af1[4] = {v2.x, v3.x, v2.y, v3.y};
                const uint2* wp = (const uint2*)(W_s + grp * RWS_H + wc + (ki + u) * 16) + tig;
                #pragma unroll
                for (int nf = 0; nf < 6; ++nf) {
                    uint2 bb = *(const uint2*)((const char*)wp + (size_t)nf * 8 * RWS_H * 2);
                    uint32_t Bf[2] = {bb.x, bb.y};
                    mma_f16(acc[0][nf], Af0, Bf);
                    mma_f16(acc[1][nf], Af1, Bf);
                }
            }
        }
    };

    auto zeroacc = [&]() {
        #pragma unroll
        for (int mf = 0; mf < 2; ++mf)
            #pragma unroll
            for (int nf = 0; nf < 6; ++nf)
                #pragma unroll
                for (int r = 0; r < 4; ++r) acc[mf][nf][r] = 0.f;
    };
    // kh0 writes its m32 rows; named bar; kh1 adds.
    auto combine = [&](float* gb) {
        if (kh == 0) {
            #pragma unroll
            for (int mf = 0; mf < 2; ++mf)
                #pragma unroll
                for (int nf = 0; nf < 6; ++nf) {
                    int m = bm0 + mf * 16 + grp, col = nf * 8 + 2 * tig;
                    *(float2*)&gb[m * 50 + col] = make_float2(acc[mf][nf][0], acc[mf][nf][1]);
                    *(float2*)&gb[(m + 8) * 50 + col] = make_float2(acc[mf][nf][2], acc[mf][nf][3]);
                }
        }
        asm volatile("bar.sync %0, 64;" :: "r"(barid) : "memory");
        if (kh == 1) {
            #pragma unroll
            for (int mf = 0; mf < 2; ++mf)
                #pragma unroll
                for (int nf = 0; nf < 6; ++nf) {
                    int m = bm0 + mf * 16 + grp, col = nf * 8 + 2 * tig;
                    float2 q0 = *(float2*)&gb[m * 50 + col];
                    float2 q1 = *(float2*)&gb[(m + 8) * 50 + col];
                    q0.x += acc[mf][nf][0]; q0.y += acc[mf][nf][1];
                    q1.x += acc[mf][nf][2]; q1.y += acc[mf][nf][3];
                    *(float2*)&gb[m * 50 + col] = q0;
                    *(float2*)&gb[(m + 8) * 50 + col] = q1;
                }
        }
    };

    for (int t = 0; t < 512; ++t) {
        zeroacc();
        if (seg == 1) {
            // ---- cross segment (off the intra-layer chain) ----
            if (layer == 0) {
                runseg(g_xp + (size_t)t * 256 + kh * 128, (size_t)512 * 256, kh * 128, 8);
            } else {
                pollflag(&g_flags[(layer - 1) * 512 + t], 43);
                const __half* hx = g_hh + (((size_t)(layer - 1) * 512 + t) * 64) * 512;
                runseg(hx + kh * 256, 512, kh * 256, 16);
            }
            combine(gbufC);
        } else {
            // ---- own segment (serial chain): W cols [KX, KX+512) ----
            if (t > 0) {
                pollflag(&g_flags[layer * 512 + t - 1], 43);
                const __half* hown = g_hh + (((size_t)layer * 512 + (t - 1)) * 64) * 512;
                runseg(hown + kh * 256, 512, KX + kh * 256, 16);
            }
            combine(gbufO);
        }
        __syncthreads();

        // ---- elementwise: 384 slots = 64 batches x 6 unit-pairs; store half2 ----
        #pragma unroll
        for (int i = 0; i < 2; ++i) {
            int s = i * 256 + tid;
            if (s < 384) {
                int b = s & 63, pr = s >> 6;             // pair 0..5
                int j0 = 2 * pr;
                float hv[2];
                #pragma unroll
                for (int jj = 0; jj < 2; ++jj) {
                    int j = j0 + jj;
                    float gi = gbufC[b * 50 + 0 * 12 + j] + gbufO[b * 50 + 0 * 12 + j] + bias_s[0 * 12 + j];
                    float gf = gbufC[b * 50 + 1 * 12 + j] + gbufO[b * 50 + 1 * 12 + j] + bias_s[1 * 12 + j];
                    float gg = gbufC[b * 50 + 2 * 12 + j] + gbufO[b * 50 + 2 * 12 + j] + bias_s[2 * 12 + j];
                    float go = gbufC[b * 50 + 3 * 12 + j] + gbufO[b * 50 + 3 * 12 + j] + bias_s[3 * 12 + j];
                    float iv = sigmoid_f(gi), fv = sigmoid_f(gf), ov = sigmoid_f(go);
                    float gt = tanh_f(gg);
                    cst[i][jj] = fv * cst[i][jj] + iv * gt;
                    hv[jj] = ov * tanh_f(cst[i][jj]);
                }
                if (j0 < nu) {
                    // logical units (u0+j0, u0+j0+1) are stored adjacent (even pair)
                    int upos = kperm16(u0 + j0);
                    __half2* dst = (__half2*)(g_hh + (((size_t)layer * 512 + t) * 64 + b) * 512 + upos);
                    *dst = __floats2half2_rn(hv[0], hv[1]);
                }
            }
        }

        __syncthreads();
        if (tid == 0)
            asm volatile("red.release.gpu.global.add.s32 [%0], %1;"
                         :: "l"(g_flags + layer * 512 + t), "r"(1) : "memory");
    }
}

// ----------------- FC head: out[64,1000] = h2[511] @ W_fc^T + b_fc -----------------
// h2 stored fp16 kperm16-permuted -> load W_fc with the same permutation.
__global__ __launch_bounds__(256) void fc_kernel(
    const float* __restrict__ Wfc, const float* __restrict__ bfc, float* __restrict__ out)
{
    __shared__ __align__(16) float Ws[4 * 512];
    const int tid = threadIdx.x;
    const int c0 = blockIdx.x * 4;

    for (int i = tid; i < 2048; i += 256) {
        int cc = i >> 9, k = i & 511;
        Ws[cc * 512 + kperm16(k)] = (c0 + cc < NCLS) ? Wfc[(size_t)(c0 + cc) * 512 + k] : 0.f;
    }
    __syncthreads();

    int b = tid & 63, ci = tid >> 6;
    int c = c0 + ci;
    if (c < NCLS) {
        const __half2* hvp = (const __half2*)(g_hh + (((size_t)2 * 512 + 511) * 64 + b) * 512);
        const float2* wvp = (const float2*)(Ws + ci * 512);
        float acc = 0.f;
        #pragma unroll 16
        for (int k = 0; k < 256; ++k) {
            float2 h2 = __half22float2(hvp[k]);
            float2 w2 = wvp[k];
            acc += h2.x * w2.x + h2.y * w2.y;
        }
        out[b * NCLS + c] = acc + bfc[c];
    }
}

// ----------------- launch -----------------
extern "C" void kernel_launch(void* const* d_in, const int* in_sizes, int n_in,
                              void* d_out, int out_size)
{
    const float* x     = (const float*)d_in[0];
    const float* Wih0  = (const float*)d_in[1];
    const float* Whh0  = (const float*)d_in[2];
    const float* bih0  = (const float*)d_in[3];
    const float* bhh0  = (const float*)d_in[4];
    const float* Wih1  = (const float*)d_in[5];
    const float* Whh1  = (const float*)d_in[6];
    const float* bih1  = (const float*)d_in[7];
    const float* bhh1  = (const float*)d_in[8];
    const float* Wih2  = (const float*)d_in[9];
    const float* Whh2  = (const float*)d_in[10];
    const float* bih2  = (const float*)d_in[11];
    const float* bhh2  = (const float*)d_in[12];
    const float* Wfc   = (const float*)d_in[13];
    const float* bfc   = (const float*)d_in[14];
    float* out = (float*)d_out;

    cudaFuncSetAttribute(lstm_fused_kernel,
                         cudaFuncAttributeMaxDynamicSharedMemorySize, FUSED_SMEM);

    zero_flags_kernel<<<3, 512>>>();
    xperm_kernel<<<8192, 256>>>(x);
    lstm_fused_kernel<<<129, 256, FUSED_SMEM>>>(
        Wih0, Whh0, bih0, bhh0, Wih1, Whh1, bih1, bhh1,
        Wih2, Whh2, bih2, bhh2);
    fc_kernel<<<250, 256>>>(Wfc, bfc, out);
}